// round 1
// baseline (speedup 1.0000x reference)
#include <cuda_runtime.h>
#include <math.h>

#define T_ 128
#define B_ 64
#define E_ 1024
#define H_ 1024
#define V_ 10000
#define M_ (T_*B_)   // 8192

// Scratch (no allocs allowed): U0 = x@W_in0^T + b0 for all t; H1 = h1 for all t.
__device__ float g_U0[(size_t)M_*H_];
__device__ float g_H1[(size_t)M_*H_];
__device__ float g_h0[2][B_*H_];

// ---------------------------------------------------------------------------
// Generic fp32 GEMM: C[M,N] = A[M,K] @ W[N,K]^T + bias, optional row gather on A.
// Tiles 64x64x16, 256 threads, 4x4 per thread.
// ---------------------------------------------------------------------------
__global__ __launch_bounds__(256)
void gemm_f32(const float* __restrict__ Abase,
              const int*   __restrict__ tok,    // null => A row m = Abase + m*K
              const float* __restrict__ W,      // [N,K] row-major
              const float* __restrict__ bias,   // [N] or null
              float* __restrict__ C, int N, int K)
{
    __shared__ float As[16][64 + 4];
    __shared__ float Ws[16][64 + 4];

    const int tid = threadIdx.x;
    const int bm  = blockIdx.y * 64;
    const int bn  = blockIdx.x * 64;

    const int row = tid >> 2;          // 0..63
    const int kq  = (tid & 3) * 4;     // 0,4,8,12

    const int am = bm + row;
    const float* arow = tok ? (Abase + (size_t)tok[am] * K)
                            : (Abase + (size_t)am * K);
    const int wn = bn + row;
    const float* wrow = (wn < N) ? (W + (size_t)wn * K) : nullptr;

    const int tx = tid & 15, ty = tid >> 4;
    float acc[4][4];
    #pragma unroll
    for (int i = 0; i < 4; i++)
        #pragma unroll
        for (int j = 0; j < 4; j++) acc[i][j] = 0.f;

    for (int k0 = 0; k0 < K; k0 += 16) {
        float4 av = *(const float4*)(arow + k0 + kq);
        float4 wv = wrow ? *(const float4*)(wrow + k0 + kq)
                         : make_float4(0.f, 0.f, 0.f, 0.f);
        __syncthreads();
        As[kq+0][row] = av.x; As[kq+1][row] = av.y;
        As[kq+2][row] = av.z; As[kq+3][row] = av.w;
        Ws[kq+0][row] = wv.x; Ws[kq+1][row] = wv.y;
        Ws[kq+2][row] = wv.z; Ws[kq+3][row] = wv.w;
        __syncthreads();
        #pragma unroll
        for (int k = 0; k < 16; k++) {
            float4 a = *(const float4*)&As[k][ty * 4];
            float4 b = *(const float4*)&Ws[k][tx * 4];
            acc[0][0] = fmaf(a.x, b.x, acc[0][0]);
            acc[0][1] = fmaf(a.x, b.y, acc[0][1]);
            acc[0][2] = fmaf(a.x, b.z, acc[0][2]);
            acc[0][3] = fmaf(a.x, b.w, acc[0][3]);
            acc[1][0] = fmaf(a.y, b.x, acc[1][0]);
            acc[1][1] = fmaf(a.y, b.y, acc[1][1]);
            acc[1][2] = fmaf(a.y, b.z, acc[1][2]);
            acc[1][3] = fmaf(a.y, b.w, acc[1][3]);
            acc[2][0] = fmaf(a.z, b.x, acc[2][0]);
            acc[2][1] = fmaf(a.z, b.y, acc[2][1]);
            acc[2][2] = fmaf(a.z, b.z, acc[2][2]);
            acc[2][3] = fmaf(a.z, b.w, acc[2][3]);
            acc[3][0] = fmaf(a.w, b.x, acc[3][0]);
            acc[3][1] = fmaf(a.w, b.y, acc[3][1]);
            acc[3][2] = fmaf(a.w, b.z, acc[3][2]);
            acc[3][3] = fmaf(a.w, b.w, acc[3][3]);
        }
    }

    const int cm = bm + ty * 4;
    const int cn = bn + tx * 4;
    #pragma unroll
    for (int i = 0; i < 4; i++) {
        #pragma unroll
        for (int j = 0; j < 4; j++) {
            int n = cn + j;
            if (n < N) {
                float v = acc[i][j];
                if (bias) v += bias[n];
                C[(size_t)(cm + i) * N + n] = v;
            }
        }
    }
}

// ---------------------------------------------------------------------------
// Layer 0 step: h0 = tanh(U[t] + h_prev @ Wh^T).   Block = 8 output columns.
// ---------------------------------------------------------------------------
__global__ __launch_bounds__(256)
void step_layer0(const float* __restrict__ h_prev,  // [B,H]
                 const float* __restrict__ Wh,      // [H,H]
                 const float* __restrict__ U,       // [B,H]
                 float* __restrict__ h_out)         // [B,H]
{
    __shared__ float Ws[8][H_];       // 32 KB: 8 weight rows
    __shared__ float hT[32][65];      // transposed h tile

    const int tid = threadIdx.x;
    const int n0  = blockIdx.x * 8;

    const float4* Wv  = (const float4*)(Wh + (size_t)n0 * H_);
    float4*       Wsv = (float4*)&Ws[0][0];
    #pragma unroll
    for (int i = 0; i < 8; i++) Wsv[tid + 256 * i] = Wv[tid + 256 * i];

    const int b  = tid & 63;
    const int cp = tid >> 6;          // 0..3 -> cols 2cp, 2cp+1
    float acc0 = 0.f, acc1 = 0.f;

    const int r  = tid >> 2;          // 0..63
    const int kk = (tid & 3) * 8;     // 0,8,16,24

    for (int k0 = 0; k0 < H_; k0 += 32) {
        __syncthreads();
        float4 v0 = *(const float4*)(h_prev + r * H_ + k0 + kk);
        float4 v1 = *(const float4*)(h_prev + r * H_ + k0 + kk + 4);
        hT[kk+0][r] = v0.x; hT[kk+1][r] = v0.y; hT[kk+2][r] = v0.z; hT[kk+3][r] = v0.w;
        hT[kk+4][r] = v1.x; hT[kk+5][r] = v1.y; hT[kk+6][r] = v1.z; hT[kk+7][r] = v1.w;
        __syncthreads();
        #pragma unroll
        for (int k = 0; k < 32; k++) {
            float hv = hT[k][b];
            acc0 = fmaf(hv, Ws[2 * cp + 0][k0 + k], acc0);
            acc1 = fmaf(hv, Ws[2 * cp + 1][k0 + k], acc1);
        }
    }
    const int n = n0 + 2 * cp;
    h_out[b * H_ + n]     = tanhf(acc0 + U[b * H_ + n]);
    h_out[b * H_ + n + 1] = tanhf(acc1 + U[b * H_ + n + 1]);
}

// ---------------------------------------------------------------------------
// Layer 1 step: h1 = tanh(h0 @ Win^T + h1_prev @ Wh^T + b).  Block = 4 columns.
// ---------------------------------------------------------------------------
__global__ __launch_bounds__(256)
void step_layer1(const float* __restrict__ h0,     // [B,H]
                 const float* __restrict__ h1p,    // [B,H]
                 const float* __restrict__ Win,    // [H,H]
                 const float* __restrict__ Wh,     // [H,H]
                 const float* __restrict__ bias,   // [H]
                 float* __restrict__ h_out)        // [B,H]
{
    __shared__ float Ws[8][H_];       // rows 0..3: Win, rows 4..7: Wh
    __shared__ float hT[32][65];

    const int tid = threadIdx.x;
    const int n0  = blockIdx.x * 4;

    {
        const float4* Wv0 = (const float4*)(Win + (size_t)n0 * H_);
        const float4* Wv1 = (const float4*)(Wh  + (size_t)n0 * H_);
        float4* Wsv = (float4*)&Ws[0][0];
        #pragma unroll
        for (int i = 0; i < 4; i++) Wsv[tid + 256 * i]        = Wv0[tid + 256 * i];
        #pragma unroll
        for (int i = 0; i < 4; i++) Wsv[1024 + tid + 256 * i] = Wv1[tid + 256 * i];
    }

    const int b = tid & 63;
    const int c = tid >> 6;           // 0..3, one output each
    const int r  = tid >> 2;
    const int kk = (tid & 3) * 8;
    float acc = 0.f;

    #pragma unroll 1
    for (int pass = 0; pass < 2; ++pass) {
        const float* src  = pass ? h1p : h0;
        const float* wrow = &Ws[pass * 4 + c][0];
        for (int k0 = 0; k0 < H_; k0 += 32) {
            __syncthreads();
            float4 v0 = *(const float4*)(src + r * H_ + k0 + kk);
            float4 v1 = *(const float4*)(src + r * H_ + k0 + kk + 4);
            hT[kk+0][r] = v0.x; hT[kk+1][r] = v0.y; hT[kk+2][r] = v0.z; hT[kk+3][r] = v0.w;
            hT[kk+4][r] = v1.x; hT[kk+5][r] = v1.y; hT[kk+6][r] = v1.z; hT[kk+7][r] = v1.w;
            __syncthreads();
            #pragma unroll
            for (int k = 0; k < 32; k++)
                acc = fmaf(hT[k][b], wrow[k0 + k], acc);
        }
    }
    const int n = n0 + c;
    h_out[b * H_ + n] = tanhf(acc + bias[n]);
}

// ---------------------------------------------------------------------------
// Final hidden state copy: out = concat(h0_final, h1_final)
// ---------------------------------------------------------------------------
__global__ void copy_final(const float* __restrict__ h0f,
                           const float* __restrict__ h1f,
                           float* __restrict__ out)
{
    int i = blockIdx.x * blockDim.x + threadIdx.x;
    if (i < B_ * H_) {
        out[i]            = h0f[i];
        out[B_ * H_ + i]  = h1f[i];
    }
}

extern "C" void kernel_launch(void* const* d_in, const int* in_sizes, int n_in,
                              void* d_out, int out_size)
{
    const float* emb    = (const float*)d_in[0];   // [V,E]
    const float* W_in0  = (const float*)d_in[1];   // [H,E]
    const float* Wh0    = (const float*)d_in[2];   // [H,H]
    const float* b0     = (const float*)d_in[3];   // [H]
    const float* W_in1  = (const float*)d_in[4];   // [H,H]
    const float* Wh1    = (const float*)d_in[5];   // [H,H]
    const float* b1     = (const float*)d_in[6];   // [H]
    const float* Wdec   = (const float*)d_in[7];   // [V,H]
    const float* bdec   = (const float*)d_in[8];   // [V]
    const float* hidden = (const float*)d_in[9];   // [L,B,H]
    const int*   tokens = (const int*)d_in[10];    // [T,B]

    float* out = (float*)d_out;
    float* logits = out;                                // [T,B,V]
    float* hfin   = out + (size_t)M_ * V_;              // [L,B,H]

    float* U0 = nullptr, *H1 = nullptr, *h0a = nullptr, *h0b = nullptr;
    cudaGetSymbolAddress((void**)&U0,  g_U0);
    cudaGetSymbolAddress((void**)&H1,  g_H1);
    cudaGetSymbolAddress((void**)&h0a, g_h0);
    h0b = h0a + B_ * H_;

    // 1) U0 = emb[tokens] @ W_in0^T + b0  (all timesteps at once)
    gemm_f32<<<dim3(H_ / 64, M_ / 64), 256>>>(emb, tokens, W_in0, b0, U0, H_, E_);

    // 2) Recurrence, 2 kernels per step
    for (int t = 0; t < T_; t++) {
        const float* h0_prev = (t == 0) ? hidden            : ((t & 1) ? h0a : h0b);
        float*       h0_cur  = (t & 1) ? h0b : h0a;
        const float* h1_prev = (t == 0) ? (hidden + B_ * H_) : (H1 + (size_t)(t - 1) * B_ * H_);
        float*       h1_cur  = H1 + (size_t)t * B_ * H_;

        step_layer0<<<H_ / 8, 256>>>(h0_prev, Wh0, U0 + (size_t)t * B_ * H_, h0_cur);
        step_layer1<<<H_ / 4, 256>>>(h0_cur, h1_prev, W_in1, Wh1, b1, h1_cur);
    }

    // 3) logits = H1 @ Wdec^T + bdec
    gemm_f32<<<dim3((V_ + 63) / 64, M_ / 64), 256>>>(H1, nullptr, Wdec, bdec,
                                                     logits, V_, H_);

    // 4) final hidden states
    const float* h0_final = (T_ & 1) ? h0a : h0b;   // T=128 even -> last write at t=127 -> h0b
    copy_final<<<(B_ * H_ + 255) / 256, 256>>>(h0b, H1 + (size_t)(T_ - 1) * B_ * H_, hfin);
    (void)h0_final; (void)in_sizes; (void)n_in; (void)out_size;
}

// round 2
// speedup vs baseline: 1.6561x; 1.6561x over previous
#include <cuda_runtime.h>
#include <math.h>

#define T_ 128
#define B_ 64
#define E_ 1024
#define H_ 1024
#define V_ 10000
#define M_ (T_*B_)   // 8192
#define BH (B_*H_)

#define GRID 128
#define NT 256
#define KT 64
#define HS_STRIDE 68          // padded row stride (floats) for h tiles
#define HB (64*HS_STRIDE)     // one h-tile buffer, in floats

// Scratch (no allocs allowed)
__device__ float g_U0[(size_t)M_*H_];
__device__ float g_H1[(size_t)M_*H_];
__device__ float g_h0[2][BH];
__device__ unsigned int g_bar[192];

// ---------------------------------------------------------------------------
// Generic fp32 GEMM: C[M,N] = A[M,K] @ W[N,K]^T + bias, optional row gather.
// ---------------------------------------------------------------------------
__global__ __launch_bounds__(256)
void gemm_f32(const float* __restrict__ Abase,
              const int*   __restrict__ tok,
              const float* __restrict__ W,
              const float* __restrict__ bias,
              float* __restrict__ C, int N, int K)
{
    __shared__ float As[16][64 + 4];
    __shared__ float Ws[16][64 + 4];

    const int tid = threadIdx.x;
    const int bm  = blockIdx.y * 64;
    const int bn  = blockIdx.x * 64;

    const int row = tid >> 2;
    const int kq  = (tid & 3) * 4;

    const int am = bm + row;
    const float* arow = tok ? (Abase + (size_t)tok[am] * K)
                            : (Abase + (size_t)am * K);
    const int wn = bn + row;
    const float* wrow = (wn < N) ? (W + (size_t)wn * K) : nullptr;

    const int tx = tid & 15, ty = tid >> 4;
    float acc[4][4];
    #pragma unroll
    for (int i = 0; i < 4; i++)
        #pragma unroll
        for (int j = 0; j < 4; j++) acc[i][j] = 0.f;

    for (int k0 = 0; k0 < K; k0 += 16) {
        float4 av = *(const float4*)(arow + k0 + kq);
        float4 wv = wrow ? *(const float4*)(wrow + k0 + kq)
                         : make_float4(0.f, 0.f, 0.f, 0.f);
        __syncthreads();
        As[kq+0][row] = av.x; As[kq+1][row] = av.y;
        As[kq+2][row] = av.z; As[kq+3][row] = av.w;
        Ws[kq+0][row] = wv.x; Ws[kq+1][row] = wv.y;
        Ws[kq+2][row] = wv.z; Ws[kq+3][row] = wv.w;
        __syncthreads();
        #pragma unroll
        for (int k = 0; k < 16; k++) {
            float4 a = *(const float4*)&As[k][ty * 4];
            float4 b = *(const float4*)&Ws[k][tx * 4];
            acc[0][0] = fmaf(a.x, b.x, acc[0][0]);
            acc[0][1] = fmaf(a.x, b.y, acc[0][1]);
            acc[0][2] = fmaf(a.x, b.z, acc[0][2]);
            acc[0][3] = fmaf(a.x, b.w, acc[0][3]);
            acc[1][0] = fmaf(a.y, b.x, acc[1][0]);
            acc[1][1] = fmaf(a.y, b.y, acc[1][1]);
            acc[1][2] = fmaf(a.y, b.z, acc[1][2]);
            acc[1][3] = fmaf(a.y, b.w, acc[1][3]);
            acc[2][0] = fmaf(a.z, b.x, acc[2][0]);
            acc[2][1] = fmaf(a.z, b.y, acc[2][1]);
            acc[2][2] = fmaf(a.z, b.z, acc[2][2]);
            acc[2][3] = fmaf(a.z, b.w, acc[2][3]);
            acc[3][0] = fmaf(a.w, b.x, acc[3][0]);
            acc[3][1] = fmaf(a.w, b.y, acc[3][1]);
            acc[3][2] = fmaf(a.w, b.z, acc[3][2]);
            acc[3][3] = fmaf(a.w, b.w, acc[3][3]);
        }
    }

    const int cm = bm + ty * 4;
    const int cn = bn + tx * 4;
    #pragma unroll
    for (int i = 0; i < 4; i++) {
        #pragma unroll
        for (int j = 0; j < 4; j++) {
            int n = cn + j;
            if (n < N) {
                float v = acc[i][j];
                if (bias) v += bias[n];
                C[(size_t)(cm + i) * N + n] = v;
            }
        }
    }
}

// ---------------------------------------------------------------------------
// Grid barrier (all GRID blocks resident by construction: 1 block/SM via smem)
// ---------------------------------------------------------------------------
__global__ void reset_bar_kernel() {
    if (threadIdx.x < 192) g_bar[threadIdx.x] = 0;
}

__device__ __forceinline__ void gsync(int slot) {
    __syncthreads();
    if (threadIdx.x == 0) {
        __threadfence();
        atomicAdd(&g_bar[slot], 1u);
        while (*((volatile unsigned int*)&g_bar[slot]) < GRID) { }
        __threadfence();
    }
    __syncthreads();
}

__device__ __forceinline__ float dot4(float4 a, float4 b, float acc) {
    acc = fmaf(a.x, b.x, acc); acc = fmaf(a.y, b.y, acc);
    acc = fmaf(a.z, b.z, acc); return fmaf(a.w, b.w, acc);
}

// ---------------------------------------------------------------------------
// One fused iteration: computes (optionally)
//   L1: h1dst = tanh(h0src @ Win1^T + h1src @ Wh1^T + b1)   (this step's h1)
//   L0: h0dst = tanh(h0src @ Wh0^T + U)                     (NEXT step's h0)
// Block handles output cols [n0, n0+8) of each matrix.
// Thread tile: 2 batches (lane, lane+32) x 2 cols, k split in halves.
// ---------------------------------------------------------------------------
template<bool L0, bool L1>
__device__ __forceinline__ void rnn_iter(
    const float* __restrict__ h0src,
    const float* __restrict__ h1src,
    const float* __restrict__ U,
    float* __restrict__ h0dst,
    float* __restrict__ h1dst,
    const float* __restrict__ sW0,
    const float* __restrict__ sWi,
    const float* __restrict__ sWh,
    float* __restrict__ hs0, float* __restrict__ hs1, float* __restrict__ red,
    float b1v0, float b1v1, int n0)
{
    const int tid   = threadIdx.x;
    const int lane  = tid & 31;
    const int cgrp  = (tid >> 5) & 3;
    const int khalf = tid >> 7;

    float a0_00=0.f, a0_01=0.f, a0_10=0.f, a0_11=0.f;
    float a1_00=0.f, a1_01=0.f, a1_10=0.f, a1_11=0.f;

    int rows[4], kcs[4];
    #pragma unroll
    for (int i = 0; i < 4; i++) {
        int lin = tid + i * NT;
        rows[i] = lin >> 4;
        kcs[i]  = (lin & 15) << 2;
    }

    // preload tile 0 into buffer 0
    float4 p0[4], p1[4];
    #pragma unroll
    for (int i = 0; i < 4; i++) {
        p0[i] = *(const float4*)&h0src[rows[i] * H_ + kcs[i]];
        if (L1) p1[i] = *(const float4*)&h1src[rows[i] * H_ + kcs[i]];
    }
    #pragma unroll
    for (int i = 0; i < 4; i++) {
        *(float4*)&hs0[rows[i] * HS_STRIDE + kcs[i]] = p0[i];
        if (L1) *(float4*)&hs1[rows[i] * HS_STRIDE + kcs[i]] = p1[i];
    }
    __syncthreads();

    int cur = 0;
    const int kl0 = khalf * 32;

    for (int tile = 0; tile < 16; ++tile) {
        if (tile < 15) {
            const int kb = (tile + 1) * KT;
            #pragma unroll
            for (int i = 0; i < 4; i++) {
                p0[i] = *(const float4*)&h0src[rows[i] * H_ + kb + kcs[i]];
                if (L1) p1[i] = *(const float4*)&h1src[rows[i] * H_ + kb + kcs[i]];
            }
        }
        const float* h0t = hs0 + cur * HB;
        const float* h1t = hs1 + cur * HB;
        const int kg0 = tile * KT + kl0;

        #pragma unroll
        for (int kk = 0; kk < 32; kk += 4) {
            const int kg = kg0 + kk;
            const int kl = kl0 + kk;
            float4 ha = *(const float4*)&h0t[lane * HS_STRIDE + kl];
            float4 hb = *(const float4*)&h0t[(lane + 32) * HS_STRIDE + kl];
            if (L0) {
                float4 w0 = *(const float4*)&sW0[(2 * cgrp    ) * H_ + kg];
                float4 w1 = *(const float4*)&sW0[(2 * cgrp + 1) * H_ + kg];
                a0_00 = dot4(ha, w0, a0_00);
                a0_01 = dot4(ha, w1, a0_01);
                a0_10 = dot4(hb, w0, a0_10);
                a0_11 = dot4(hb, w1, a0_11);
            }
            if (L1) {
                float4 wi0 = *(const float4*)&sWi[(2 * cgrp    ) * H_ + kg];
                float4 wi1 = *(const float4*)&sWi[(2 * cgrp + 1) * H_ + kg];
                a1_00 = dot4(ha, wi0, a1_00);
                a1_01 = dot4(ha, wi1, a1_01);
                a1_10 = dot4(hb, wi0, a1_10);
                a1_11 = dot4(hb, wi1, a1_11);
                float4 ga = *(const float4*)&h1t[lane * HS_STRIDE + kl];
                float4 gb = *(const float4*)&h1t[(lane + 32) * HS_STRIDE + kl];
                float4 wh0 = *(const float4*)&sWh[(2 * cgrp    ) * H_ + kg];
                float4 wh1 = *(const float4*)&sWh[(2 * cgrp + 1) * H_ + kg];
                a1_00 = dot4(ga, wh0, a1_00);
                a1_01 = dot4(ga, wh1, a1_01);
                a1_10 = dot4(gb, wh0, a1_10);
                a1_11 = dot4(gb, wh1, a1_11);
            }
        }

        if (tile < 15) {
            float* d0 = hs0 + (1 - cur) * HB;
            float* d1 = hs1 + (1 - cur) * HB;
            #pragma unroll
            for (int i = 0; i < 4; i++) {
                *(float4*)&d0[rows[i] * HS_STRIDE + kcs[i]] = p0[i];
                if (L1) *(float4*)&d1[rows[i] * HS_STRIDE + kcs[i]] = p1[i];
            }
        }
        __syncthreads();
        cur ^= 1;
    }

    // k-split reduction + epilogue
    float* r = red + (cgrp * 32 + lane) * 8;
    if (khalf == 1) {
        r[0] = a0_00; r[1] = a0_01; r[2] = a0_10; r[3] = a0_11;
        r[4] = a1_00; r[5] = a1_01; r[6] = a1_10; r[7] = a1_11;
    }
    __syncthreads();
    if (khalf == 0) {
        a0_00 += r[0]; a0_01 += r[1]; a0_10 += r[2]; a0_11 += r[3];
        a1_00 += r[4]; a1_01 += r[5]; a1_10 += r[6]; a1_11 += r[7];
        const int nA = n0 + 2 * cgrp, nB = nA + 1;
        const int bA = lane, bB = lane + 32;
        if (L1) {
            h1dst[bA * H_ + nA] = tanhf(a1_00 + b1v0);
            h1dst[bA * H_ + nB] = tanhf(a1_01 + b1v1);
            h1dst[bB * H_ + nA] = tanhf(a1_10 + b1v0);
            h1dst[bB * H_ + nB] = tanhf(a1_11 + b1v1);
        }
        if (L0) {
            h0dst[bA * H_ + nA] = tanhf(a0_00 + U[bA * H_ + nA]);
            h0dst[bA * H_ + nB] = tanhf(a0_01 + U[bA * H_ + nB]);
            h0dst[bB * H_ + nA] = tanhf(a0_10 + U[bB * H_ + nA]);
            h0dst[bB * H_ + nB] = tanhf(a0_11 + U[bB * H_ + nB]);
        }
    }
    // `red` reuse next iteration is protected by the following gsync.
}

// ---------------------------------------------------------------------------
// Persistent recurrence kernel: all 128 timesteps in one launch.
// ---------------------------------------------------------------------------
__global__ __launch_bounds__(NT, 1)
void rnn_persistent(const float* __restrict__ Wh0,
                    const float* __restrict__ Win1,
                    const float* __restrict__ Wh1,
                    const float* __restrict__ b1,
                    const float* __restrict__ hidden)
{
    extern __shared__ float sm[];
    float* sW0 = sm;                    // 8*1024
    float* sWi = sW0 + 8 * H_;          // 8*1024
    float* sWh = sWi + 8 * H_;          // 8*1024
    float* hs0 = sWh + 8 * H_;          // 2*HB
    float* hs1 = hs0 + 2 * HB;          // 2*HB
    float* red = hs1 + 2 * HB;          // 128*8

    const int n0  = blockIdx.x * 8;
    const int tid = threadIdx.x;

    // Load the 8 weight rows of each matrix (contiguous in row-major [H][H]).
    {
        const float4* a = (const float4*)(Wh0  + (size_t)n0 * H_);
        const float4* b = (const float4*)(Win1 + (size_t)n0 * H_);
        const float4* c = (const float4*)(Wh1  + (size_t)n0 * H_);
        float4* d0 = (float4*)sW0; float4* d1 = (float4*)sWi; float4* d2 = (float4*)sWh;
        #pragma unroll
        for (int i = 0; i < 8; i++) {
            d0[tid + i * NT] = a[tid + i * NT];
            d1[tid + i * NT] = b[tid + i * NT];
            d2[tid + i * NT] = c[tid + i * NT];
        }
    }
    float b1v0, b1v1;
    {
        int cgrp = (tid >> 5) & 3;
        b1v0 = b1[n0 + 2 * cgrp];
        b1v1 = b1[n0 + 2 * cgrp + 1];
    }
    __syncthreads();

    int slot = 0;

    // Prologue: h0(0) = tanh(hidden[0] @ Wh0^T + U0[0])
    rnn_iter<true, false>(hidden, nullptr, g_U0, g_h0[0], nullptr,
                          sW0, sWi, sWh, hs0, hs1, red, b1v0, b1v1, n0);
    gsync(slot++);

    for (int t = 0; t < T_; ++t) {
        const float* h0s = g_h0[t & 1];
        const float* h1s = (t == 0) ? (hidden + BH) : (g_H1 + (size_t)(t - 1) * BH);
        float*       h1d = g_H1 + (size_t)t * BH;
        if (t < T_ - 1) {
            rnn_iter<true, true>(h0s, h1s, g_U0 + (size_t)(t + 1) * BH,
                                 g_h0[(t + 1) & 1], h1d,
                                 sW0, sWi, sWh, hs0, hs1, red, b1v0, b1v1, n0);
        } else {
            rnn_iter<false, true>(h0s, h1s, nullptr, nullptr, h1d,
                                  sW0, sWi, sWh, hs0, hs1, red, b1v0, b1v1, n0);
        }
        gsync(slot++);
    }
}

// ---------------------------------------------------------------------------
// Final hidden state copy
// ---------------------------------------------------------------------------
__global__ void copy_final(const float* __restrict__ h0f,
                           const float* __restrict__ h1f,
                           float* __restrict__ out)
{
    int i = blockIdx.x * blockDim.x + threadIdx.x;
    if (i < BH) {
        out[i]       = h0f[i];
        out[BH + i]  = h1f[i];
    }
}

extern "C" void kernel_launch(void* const* d_in, const int* in_sizes, int n_in,
                              void* d_out, int out_size)
{
    const float* emb    = (const float*)d_in[0];   // [V,E]
    const float* W_in0  = (const float*)d_in[1];   // [H,E]
    const float* Wh0    = (const float*)d_in[2];   // [H,H]
    const float* b0     = (const float*)d_in[3];   // [H]
    const float* W_in1  = (const float*)d_in[4];   // [H,H]
    const float* Wh1    = (const float*)d_in[5];   // [H,H]
    const float* b1     = (const float*)d_in[6];   // [H]
    const float* Wdec   = (const float*)d_in[7];   // [V,H]
    const float* bdec   = (const float*)d_in[8];   // [V]
    const float* hidden = (const float*)d_in[9];   // [L,B,H]
    const int*   tokens = (const int*)d_in[10];    // [T,B]

    float* out    = (float*)d_out;
    float* logits = out;                            // [T,B,V]
    float* hfin   = out + (size_t)M_ * V_;          // [L,B,H]

    float* U0 = nullptr, *H1 = nullptr, *h0a = nullptr;
    cudaGetSymbolAddress((void**)&U0,  g_U0);
    cudaGetSymbolAddress((void**)&H1,  g_H1);
    cudaGetSymbolAddress((void**)&h0a, g_h0);

    const size_t smem_bytes = (3 * 8 * H_ + 4 * HB + 128 * 8) * sizeof(float);
    cudaFuncSetAttribute(rnn_persistent,
                         cudaFuncAttributeMaxDynamicSharedMemorySize,
                         (int)smem_bytes);

    // 1) U0 = emb[tokens] @ W_in0^T + b0  (all timesteps at once)
    gemm_f32<<<dim3(H_ / 64, M_ / 64), 256>>>(emb, tokens, W_in0, b0, U0, H_, E_);

    // 2) Persistent recurrence (all 128 steps, one launch)
    reset_bar_kernel<<<1, 256>>>();
    rnn_persistent<<<GRID, NT, smem_bytes>>>(Wh0, W_in1, Wh1, b1, hidden);

    // 3) logits = H1 @ Wdec^T + bdec
    gemm_f32<<<dim3((V_ + 63) / 64, M_ / 64), 256>>>(H1, nullptr, Wdec, bdec,
                                                     logits, V_, H_);

    // 4) final hidden states: h0(127) lives in g_h0[1], h1(127) in H1[127]
    copy_final<<<(BH + 255) / 256, 256>>>(h0a + BH, H1 + (size_t)(T_ - 1) * BH, hfin);

    (void)b0; (void)in_sizes; (void)n_in; (void)out_size;
}

// round 5
// speedup vs baseline: 2.5755x; 1.5552x over previous
#include <cuda_runtime.h>
#include <cuda_bf16.h>
#include <math.h>
#include <stdint.h>

#define T_ 128
#define B_ 64
#define E_ 1024
#define H_ 1024
#define V_ 10000
#define VP 10112              // V padded to 128 (79*128)
#define M_ (T_*B_)            // 8192
#define BH (B_*H_)
#define K3 3072               // [Ah|Ah|Al] x [Bh|Bl|Bh] 3-term split

#define GRID 128
#define NT 256
#define KT 64
#define HS_STRIDE 68
#define HB (64*HS_STRIDE)

// Scratch (no allocs allowed)
__device__ float g_U0[(size_t)M_*H_];
__device__ float g_H1[(size_t)M_*H_];
__device__ float g_h0[2][BH];
__device__ unsigned int g_bar[192];
__device__ __nv_bfloat16 g_A3[(size_t)M_*K3];   // H1 split: [Ah(1024)|Ah(1024)|Al(1024)]
__device__ __nv_bfloat16 g_B3[(size_t)VP*K3];   // Wdec split: [Bh|Bl|Bh], pad rows zero

// ===========================================================================
// fp32 GEMM (embedding projection)
// ===========================================================================
__global__ __launch_bounds__(256)
void gemm_f32(const float* __restrict__ Abase,
              const int*   __restrict__ tok,
              const float* __restrict__ W,
              const float* __restrict__ bias,
              float* __restrict__ C, int N, int K)
{
    __shared__ float As[16][64 + 4];
    __shared__ float Ws[16][64 + 4];

    const int tid = threadIdx.x;
    const int bm  = blockIdx.y * 64;
    const int bn  = blockIdx.x * 64;

    const int row = tid >> 2;
    const int kq  = (tid & 3) * 4;

    const int am = bm + row;
    const float* arow = tok ? (Abase + (size_t)tok[am] * K)
                            : (Abase + (size_t)am * K);
    const int wn = bn + row;
    const float* wrow = (wn < N) ? (W + (size_t)wn * K) : nullptr;

    const int tx = tid & 15, ty = tid >> 4;
    float acc[4][4];
    #pragma unroll
    for (int i = 0; i < 4; i++)
        #pragma unroll
        for (int j = 0; j < 4; j++) acc[i][j] = 0.f;

    for (int k0 = 0; k0 < K; k0 += 16) {
        float4 av = *(const float4*)(arow + k0 + kq);
        float4 wv = wrow ? *(const float4*)(wrow + k0 + kq)
                         : make_float4(0.f, 0.f, 0.f, 0.f);
        __syncthreads();
        As[kq+0][row] = av.x; As[kq+1][row] = av.y;
        As[kq+2][row] = av.z; As[kq+3][row] = av.w;
        Ws[kq+0][row] = wv.x; Ws[kq+1][row] = wv.y;
        Ws[kq+2][row] = wv.z; Ws[kq+3][row] = wv.w;
        __syncthreads();
        #pragma unroll
        for (int k = 0; k < 16; k++) {
            float4 a = *(const float4*)&As[k][ty * 4];
            float4 b = *(const float4*)&Ws[k][tx * 4];
            acc[0][0] = fmaf(a.x, b.x, acc[0][0]);
            acc[0][1] = fmaf(a.x, b.y, acc[0][1]);
            acc[0][2] = fmaf(a.x, b.z, acc[0][2]);
            acc[0][3] = fmaf(a.x, b.w, acc[0][3]);
            acc[1][0] = fmaf(a.y, b.x, acc[1][0]);
            acc[1][1] = fmaf(a.y, b.y, acc[1][1]);
            acc[1][2] = fmaf(a.y, b.z, acc[1][2]);
            acc[1][3] = fmaf(a.y, b.w, acc[1][3]);
            acc[2][0] = fmaf(a.z, b.x, acc[2][0]);
            acc[2][1] = fmaf(a.z, b.y, acc[2][1]);
            acc[2][2] = fmaf(a.z, b.z, acc[2][2]);
            acc[2][3] = fmaf(a.z, b.w, acc[2][3]);
            acc[3][0] = fmaf(a.w, b.x, acc[3][0]);
            acc[3][1] = fmaf(a.w, b.y, acc[3][1]);
            acc[3][2] = fmaf(a.w, b.z, acc[3][2]);
            acc[3][3] = fmaf(a.w, b.w, acc[3][3]);
        }
    }

    const int cm = bm + ty * 4;
    const int cn = bn + tx * 4;
    #pragma unroll
    for (int i = 0; i < 4; i++) {
        #pragma unroll
        for (int j = 0; j < 4; j++) {
            int n = cn + j;
            if (n < N) {
                float v = acc[i][j];
                if (bias) v += bias[n];
                C[(size_t)(cm + i) * N + n] = v;
            }
        }
    }
}

// ===========================================================================
// Grid barrier
// ===========================================================================
__global__ void reset_bar_kernel() {
    if (threadIdx.x < 192) g_bar[threadIdx.x] = 0;
}

__device__ __forceinline__ void gsync(int slot) {
    __syncthreads();
    if (threadIdx.x == 0) {
        __threadfence();
        atomicAdd(&g_bar[slot], 1u);
        while (*((volatile unsigned int*)&g_bar[slot]) < GRID) { }
        __threadfence();
    }
    __syncthreads();
}

__device__ __forceinline__ float dot4(float4 a, float4 b, float acc) {
    acc = fmaf(a.x, b.x, acc); acc = fmaf(a.y, b.y, acc);
    acc = fmaf(a.z, b.z, acc); return fmaf(a.w, b.w, acc);
}

__device__ __forceinline__ void split_bf16(float x, __nv_bfloat16& h, __nv_bfloat16& l) {
    h = __float2bfloat16(x);
    l = __float2bfloat16(x - __bfloat162float(h));
}

// ===========================================================================
// Fused recurrence iteration + split h1 store into g_A3 [Ah|Ah|Al]
// ===========================================================================
template<bool L0, bool L1>
__device__ __forceinline__ void rnn_iter(
    const float* __restrict__ h0src,
    const float* __restrict__ h1src,
    const float* __restrict__ U,
    float* __restrict__ h0dst,
    float* __restrict__ h1dst,
    __nv_bfloat16* __restrict__ a3,       // row base for timestep t (K3 stride)
    const float* __restrict__ sW0,
    const float* __restrict__ sWi,
    const float* __restrict__ sWh,
    float* __restrict__ hs0, float* __restrict__ hs1, float* __restrict__ red,
    float b1v0, float b1v1, int n0)
{
    const int tid   = threadIdx.x;
    const int lane  = tid & 31;
    const int cgrp  = (tid >> 5) & 3;
    const int khalf = tid >> 7;

    float a0_00=0.f, a0_01=0.f, a0_10=0.f, a0_11=0.f;
    float a1_00=0.f, a1_01=0.f, a1_10=0.f, a1_11=0.f;

    int rows[4], kcs[4];
    #pragma unroll
    for (int i = 0; i < 4; i++) {
        int lin = tid + i * NT;
        rows[i] = lin >> 4;
        kcs[i]  = (lin & 15) << 2;
    }

    float4 p0[4], p1[4];
    #pragma unroll
    for (int i = 0; i < 4; i++) {
        p0[i] = *(const float4*)&h0src[rows[i] * H_ + kcs[i]];
        if (L1) p1[i] = *(const float4*)&h1src[rows[i] * H_ + kcs[i]];
    }
    #pragma unroll
    for (int i = 0; i < 4; i++) {
        *(float4*)&hs0[rows[i] * HS_STRIDE + kcs[i]] = p0[i];
        if (L1) *(float4*)&hs1[rows[i] * HS_STRIDE + kcs[i]] = p1[i];
    }
    __syncthreads();

    int cur = 0;
    const int kl0 = khalf * 32;

    for (int tile = 0; tile < 16; ++tile) {
        if (tile < 15) {
            const int kb = (tile + 1) * KT;
            #pragma unroll
            for (int i = 0; i < 4; i++) {
                p0[i] = *(const float4*)&h0src[rows[i] * H_ + kb + kcs[i]];
                if (L1) p1[i] = *(const float4*)&h1src[rows[i] * H_ + kb + kcs[i]];
            }
        }
        const float* h0t = hs0 + cur * HB;
        const float* h1t = hs1 + cur * HB;
        const int kg0 = tile * KT + kl0;

        #pragma unroll
        for (int kk = 0; kk < 32; kk += 4) {
            const int kg = kg0 + kk;
            const int kl = kl0 + kk;
            float4 ha = *(const float4*)&h0t[lane * HS_STRIDE + kl];
            float4 hb = *(const float4*)&h0t[(lane + 32) * HS_STRIDE + kl];
            if (L0) {
                float4 w0 = *(const float4*)&sW0[(2 * cgrp    ) * H_ + kg];
                float4 w1 = *(const float4*)&sW0[(2 * cgrp + 1) * H_ + kg];
                a0_00 = dot4(ha, w0, a0_00);
                a0_01 = dot4(ha, w1, a0_01);
                a0_10 = dot4(hb, w0, a0_10);
                a0_11 = dot4(hb, w1, a0_11);
            }
            if (L1) {
                float4 wi0 = *(const float4*)&sWi[(2 * cgrp    ) * H_ + kg];
                float4 wi1 = *(const float4*)&sWi[(2 * cgrp + 1) * H_ + kg];
                a1_00 = dot4(ha, wi0, a1_00);
                a1_01 = dot4(ha, wi1, a1_01);
                a1_10 = dot4(hb, wi0, a1_10);
                a1_11 = dot4(hb, wi1, a1_11);
                float4 ga = *(const float4*)&h1t[lane * HS_STRIDE + kl];
                float4 gb = *(const float4*)&h1t[(lane + 32) * HS_STRIDE + kl];
                float4 wh0 = *(const float4*)&sWh[(2 * cgrp    ) * H_ + kg];
                float4 wh1 = *(const float4*)&sWh[(2 * cgrp + 1) * H_ + kg];
                a1_00 = dot4(ga, wh0, a1_00);
                a1_01 = dot4(ga, wh1, a1_01);
                a1_10 = dot4(gb, wh0, a1_10);
                a1_11 = dot4(gb, wh1, a1_11);
            }
        }

        if (tile < 15) {
            float* d0 = hs0 + (1 - cur) * HB;
            float* d1 = hs1 + (1 - cur) * HB;
            #pragma unroll
            for (int i = 0; i < 4; i++) {
                *(float4*)&d0[rows[i] * HS_STRIDE + kcs[i]] = p0[i];
                if (L1) *(float4*)&d1[rows[i] * HS_STRIDE + kcs[i]] = p1[i];
            }
        }
        __syncthreads();
        cur ^= 1;
    }

    float* r = red + (cgrp * 32 + lane) * 8;
    if (khalf == 1) {
        r[0] = a0_00; r[1] = a0_01; r[2] = a0_10; r[3] = a0_11;
        r[4] = a1_00; r[5] = a1_01; r[6] = a1_10; r[7] = a1_11;
    }
    __syncthreads();
    if (khalf == 0) {
        a0_00 += r[0]; a0_01 += r[1]; a0_10 += r[2]; a0_11 += r[3];
        a1_00 += r[4]; a1_01 += r[5]; a1_10 += r[6]; a1_11 += r[7];
        const int nA = n0 + 2 * cgrp, nB = nA + 1;
        const int bA = lane, bB = lane + 32;
        if (L1) {
            float v00 = tanhf(a1_00 + b1v0);
            float v01 = tanhf(a1_01 + b1v1);
            float v10 = tanhf(a1_10 + b1v0);
            float v11 = tanhf(a1_11 + b1v1);
            h1dst[bA * H_ + nA] = v00;
            h1dst[bA * H_ + nB] = v01;
            h1dst[bB * H_ + nA] = v10;
            h1dst[bB * H_ + nB] = v11;
            __nv_bfloat16 hh, ll;
            // A3 layout per row: [Ah(0..1023) | Ah(1024..2047) | Al(2048..3071)]
            split_bf16(v00, hh, ll);
            a3[(size_t)bA*K3+nA]=hh; a3[(size_t)bA*K3+1024+nA]=hh; a3[(size_t)bA*K3+2048+nA]=ll;
            split_bf16(v01, hh, ll);
            a3[(size_t)bA*K3+nB]=hh; a3[(size_t)bA*K3+1024+nB]=hh; a3[(size_t)bA*K3+2048+nB]=ll;
            split_bf16(v10, hh, ll);
            a3[(size_t)bB*K3+nA]=hh; a3[(size_t)bB*K3+1024+nA]=hh; a3[(size_t)bB*K3+2048+nA]=ll;
            split_bf16(v11, hh, ll);
            a3[(size_t)bB*K3+nB]=hh; a3[(size_t)bB*K3+1024+nB]=hh; a3[(size_t)bB*K3+2048+nB]=ll;
        }
        if (L0) {
            h0dst[bA * H_ + nA] = tanhf(a0_00 + U[bA * H_ + nA]);
            h0dst[bA * H_ + nB] = tanhf(a0_01 + U[bA * H_ + nB]);
            h0dst[bB * H_ + nA] = tanhf(a0_10 + U[bB * H_ + nA]);
            h0dst[bB * H_ + nB] = tanhf(a0_11 + U[bB * H_ + nB]);
        }
    }
}

__global__ __launch_bounds__(NT, 1)
void rnn_persistent(const float* __restrict__ Wh0,
                    const float* __restrict__ Win1,
                    const float* __restrict__ Wh1,
                    const float* __restrict__ b1,
                    const float* __restrict__ hidden)
{
    extern __shared__ float sm[];
    float* sW0 = sm;
    float* sWi = sW0 + 8 * H_;
    float* sWh = sWi + 8 * H_;
    float* hs0 = sWh + 8 * H_;
    float* hs1 = hs0 + 2 * HB;
    float* red = hs1 + 2 * HB;

    const int n0  = blockIdx.x * 8;
    const int tid = threadIdx.x;

    {
        const float4* a = (const float4*)(Wh0  + (size_t)n0 * H_);
        const float4* b = (const float4*)(Win1 + (size_t)n0 * H_);
        const float4* c = (const float4*)(Wh1  + (size_t)n0 * H_);
        float4* d0 = (float4*)sW0; float4* d1 = (float4*)sWi; float4* d2 = (float4*)sWh;
        #pragma unroll
        for (int i = 0; i < 8; i++) {
            d0[tid + i * NT] = a[tid + i * NT];
            d1[tid + i * NT] = b[tid + i * NT];
            d2[tid + i * NT] = c[tid + i * NT];
        }
    }
    float b1v0, b1v1;
    {
        int cgrp = (tid >> 5) & 3;
        b1v0 = b1[n0 + 2 * cgrp];
        b1v1 = b1[n0 + 2 * cgrp + 1];
    }
    __syncthreads();

    int slot = 0;

    rnn_iter<true, false>(hidden, nullptr, g_U0, g_h0[0], nullptr, nullptr,
                          sW0, sWi, sWh, hs0, hs1, red, b1v0, b1v1, n0);
    gsync(slot++);

    for (int t = 0; t < T_; ++t) {
        const float* h0s = g_h0[t & 1];
        const float* h1s = (t == 0) ? (hidden + BH) : (g_H1 + (size_t)(t - 1) * BH);
        float*         h1d = g_H1 + (size_t)t * BH;
        __nv_bfloat16* a3  = g_A3 + (size_t)t * B_ * K3;
        if (t < T_ - 1) {
            rnn_iter<true, true>(h0s, h1s, g_U0 + (size_t)(t + 1) * BH,
                                 g_h0[(t + 1) & 1], h1d, a3,
                                 sW0, sWi, sWh, hs0, hs1, red, b1v0, b1v1, n0);
        } else {
            rnn_iter<false, true>(h0s, h1s, nullptr, nullptr, h1d, a3,
                                  sW0, sWi, sWh, hs0, hs1, red, b1v0, b1v1, n0);
        }
        gsync(slot++);
    }
}

// ===========================================================================
// Wdec fp32 -> bf16 [Bh|Bl|Bh] split (K3 layout, pad rows zero)
// ===========================================================================
__global__ __launch_bounds__(256)
void convert_wdec(const float* __restrict__ W, __nv_bfloat16* __restrict__ B3)
{
    size_t i = (size_t)blockIdx.x * 256 + threadIdx.x;   // over VP*1024
    int n = (int)(i >> 10);
    int k = (int)(i & 1023);
    float v = (n < V_) ? W[(size_t)n * H_ + k] : 0.f;
    __nv_bfloat16 h, l;
    split_bf16(v, h, l);
    B3[(size_t)n * K3 + k]        = h;
    B3[(size_t)n * K3 + 1024 + k] = l;
    B3[(size_t)n * K3 + 2048 + k] = h;
}

// ===========================================================================
// mma.sync bf16 decoder GEMM: C = A3 @ B3^T + bdec, K=3072
//   A3·B3 index-paired = Ah·Bh + Ah·Bl + Al·Bh  (3-term split)
// CTA 128x128, 8 warps (2x4), warp tile 64x32, BK=64, cp.async double-buffer.
// ===========================================================================
#define DEC_SMEM 65536   // 2 bufs x (A 16KB + B 16KB)

__device__ __forceinline__ uint32_t smem_u32(const void* p) {
    uint32_t a;
    asm("{ .reg .u64 t; cvta.to.shared.u64 t, %1; cvt.u32.u64 %0, t; }"
        : "=r"(a) : "l"(p));
    return a;
}
__device__ __forceinline__ void cp16(uint32_t dst, const void* src) {
    asm volatile("cp.async.cg.shared.global [%0], [%1], 16;"
                 :: "r"(dst), "l"(src));
}
__device__ __forceinline__ void ldm_x4(uint32_t& r0, uint32_t& r1,
                                       uint32_t& r2, uint32_t& r3, uint32_t addr) {
    asm volatile("ldmatrix.sync.aligned.m8n8.x4.shared.b16 {%0,%1,%2,%3}, [%4];"
                 : "=r"(r0), "=r"(r1), "=r"(r2), "=r"(r3) : "r"(addr));
}
__device__ __forceinline__ void mma16816(float& d0, float& d1, float& d2, float& d3,
                                         uint32_t a0, uint32_t a1, uint32_t a2, uint32_t a3,
                                         uint32_t b0, uint32_t b1) {
    asm volatile("mma.sync.aligned.m16n8k16.row.col.f32.bf16.bf16.f32 "
                 "{%0,%1,%2,%3}, {%4,%5,%6,%7}, {%8,%9}, {%0,%1,%2,%3};"
                 : "+f"(d0), "+f"(d1), "+f"(d2), "+f"(d3)
                 : "r"(a0), "r"(a1), "r"(a2), "r"(a3), "r"(b0), "r"(b1));
}

__global__ __launch_bounds__(256, 1)
void decoder_mma(const __nv_bfloat16* __restrict__ A3,
                 const __nv_bfloat16* __restrict__ B3,
                 const float* __restrict__ bdec, float* __restrict__ C)
{
    extern __shared__ char dsm[];
    const uint32_t sb = smem_u32(dsm);

    const int tid  = threadIdx.x;
    const int lane = tid & 31, wid = tid >> 5;
    const int wm = wid >> 2, wn = wid & 3;            // 2 x 4 warp grid
    const int m0 = blockIdx.y * 128, n0 = blockIdx.x * 128;

    float acc[4][4][4];
    #pragma unroll
    for (int i = 0; i < 4; i++)
        #pragma unroll
        for (int j = 0; j < 4; j++)
            #pragma unroll
            for (int q = 0; q < 4; q++) acc[i][j][q] = 0.f;

    int lrow[4], lcb[4];
    #pragma unroll
    for (int i = 0; i < 4; i++) {
        int idx = tid + i * 256;
        lrow[i] = idx >> 3;
        lcb[i]  = (idx & 7) * 16;
    }

    #define LOAD_TILE(ch, buf) do {                                            \
        const uint32_t Ab_ = sb + (buf) * 32768;                               \
        const uint32_t Bb_ = Ab_ + 16384;                                      \
        _Pragma("unroll")                                                      \
        for (int i_ = 0; i_ < 4; i_++) {                                       \
            int r_ = lrow[i_], cb_ = lcb[i_];                                  \
            uint32_t sw_ = (uint32_t)(cb_ ^ ((r_ & 7) << 4));                  \
            cp16(Ab_ + r_ * 128 + sw_,                                         \
                 (const char*)A3 + (((size_t)(m0 + r_) * K3 + (ch) * 64) * 2 + cb_)); \
            cp16(Bb_ + r_ * 128 + sw_,                                         \
                 (const char*)B3 + (((size_t)(n0 + r_) * K3 + (ch) * 64) * 2 + cb_)); \
        }                                                                      \
        asm volatile("cp.async.commit_group;");                                \
    } while (0)

    LOAD_TILE(0, 0);

    const int KCH = K3 / 64;   // 48
    for (int ch = 0; ch < KCH; ++ch) {
        if (ch + 1 < KCH) {
            LOAD_TILE(ch + 1, (ch + 1) & 1);
            asm volatile("cp.async.wait_group 1;");
        } else {
            asm volatile("cp.async.wait_group 0;");
        }
        __syncthreads();

        const uint32_t Ab = sb + (ch & 1) * 32768;
        const uint32_t Bb = Ab + 16384;

        #pragma unroll
        for (int ks = 0; ks < 4; ++ks) {
            const int kb2 = ks * 32;   // byte offset of this k16

            uint32_t b[8];
            #pragma unroll
            for (int h = 0; h < 2; ++h) {
                int nrow = wn * 32 + h * 16 + ((lane >> 4) & 1) * 8 + (lane & 7);
                int kcol = kb2 + ((lane >> 3) & 1) * 16;
                uint32_t ad = Bb + nrow * 128 + (kcol ^ ((nrow & 7) << 4));
                ldm_x4(b[4*h+0], b[4*h+1], b[4*h+2], b[4*h+3], ad);
            }

            #pragma unroll
            for (int mf = 0; mf < 4; ++mf) {
                int arow = wm * 64 + mf * 16 + (lane & 15);
                int acol = kb2 + ((lane >> 4) & 1) * 16;
                uint32_t ad = Ab + arow * 128 + (acol ^ ((arow & 7) << 4));
                uint32_t a0, a1, a2r, a3r;
                ldm_x4(a0, a1, a2r, a3r, ad);
                #pragma unroll
                for (int nf = 0; nf < 4; ++nf)
                    mma16816(acc[mf][nf][0], acc[mf][nf][1],
                             acc[mf][nf][2], acc[mf][nf][3],
                             a0, a1, a2r, a3r, b[nf*2], b[nf*2+1]);
            }
        }
        __syncthreads();
    }

    #pragma unroll
    for (int mf = 0; mf < 4; ++mf) {
        const int r0 = m0 + wm * 64 + mf * 16 + (lane >> 2);
        #pragma unroll
        for (int nf = 0; nf < 4; ++nf) {
            const int c = n0 + wn * 32 + nf * 8 + (lane & 3) * 2;
            if (c < V_) {
                float2 bia = *(const float2*)(bdec + c);
                float2 v0 = make_float2(acc[mf][nf][0] + bia.x, acc[mf][nf][1] + bia.y);
                float2 v1 = make_float2(acc[mf][nf][2] + bia.x, acc[mf][nf][3] + bia.y);
                *(float2*)(C + (size_t)r0 * V_ + c)       = v0;
                *(float2*)(C + (size_t)(r0+8) * V_ + c)   = v1;
            }
        }
    }
}

// ===========================================================================
// Final hidden state copy
// ===========================================================================
__global__ void copy_final(const float* __restrict__ h0f,
                           const float* __restrict__ h1f,
                           float* __restrict__ out)
{
    int i = blockIdx.x * blockDim.x + threadIdx.x;
    if (i < BH) {
        out[i]      = h0f[i];
        out[BH + i] = h1f[i];
    }
}

extern "C" void kernel_launch(void* const* d_in, const int* in_sizes, int n_in,
                              void* d_out, int out_size)
{
    const float* emb    = (const float*)d_in[0];
    const float* W_in0  = (const float*)d_in[1];
    const float* Wh0    = (const float*)d_in[2];
    const float* b0     = (const float*)d_in[3];
    const float* W_in1  = (const float*)d_in[4];
    const float* Wh1    = (const float*)d_in[5];
    const float* b1     = (const float*)d_in[6];
    const float* Wdec   = (const float*)d_in[7];
    const float* bdec   = (const float*)d_in[8];
    const float* hidden = (const float*)d_in[9];
    const int*   tokens = (const int*)d_in[10];

    float* out    = (float*)d_out;
    float* logits = out;
    float* hfin   = out + (size_t)M_ * V_;

    float *U0 = nullptr, *H1 = nullptr, *h0a = nullptr;
    __nv_bfloat16 *A3 = nullptr, *B3 = nullptr;
    cudaGetSymbolAddress((void**)&U0,  g_U0);
    cudaGetSymbolAddress((void**)&H1,  g_H1);
    cudaGetSymbolAddress((void**)&h0a, g_h0);
    cudaGetSymbolAddress((void**)&A3,  g_A3);
    cudaGetSymbolAddress((void**)&B3,  g_B3);

    const size_t rec_smem = (3 * 8 * H_ + 4 * HB + 128 * 8) * sizeof(float);
    cudaFuncSetAttribute(rnn_persistent,
                         cudaFuncAttributeMaxDynamicSharedMemorySize, (int)rec_smem);
    cudaFuncSetAttribute(decoder_mma,
                         cudaFuncAttributeMaxDynamicSharedMemorySize, DEC_SMEM);

    // 0) Wdec -> bf16 [Bh|Bl|Bh] (independent)
    convert_wdec<<<(int)(((size_t)VP * 1024) / 256), 256>>>(Wdec, B3);

    // 1) U0 = emb[tokens] @ W_in0^T + b0
    gemm_f32<<<dim3(H_ / 64, M_ / 64), 256>>>(emb, tokens, W_in0, b0, U0, H_, E_);

    // 2) Persistent recurrence (writes fp32 H1 + [Ah|Ah|Al] A3)
    reset_bar_kernel<<<1, 256>>>();
    rnn_persistent<<<GRID, NT, rec_smem>>>(Wh0, W_in1, Wh1, b1, hidden);

    // 3) logits = A3 @ B3^T + bdec via mma.sync bf16 (K=3072, 3-term split)
    decoder_mma<<<dim3(VP / 128, M_ / 128), 256, DEC_SMEM>>>(A3, B3, bdec, logits);

    // 4) final hidden states
    copy_final<<<(BH + 255) / 256, 256>>>(h0a + BH, H1 + (size_t)(T_ - 1) * BH, hfin);

    (void)b0; (void)in_sizes; (void)n_in; (void)out_size;
}

// round 6
// speedup vs baseline: 3.7963x; 1.4740x over previous
#include <cuda_runtime.h>
#include <cuda_bf16.h>
#include <math.h>
#include <stdint.h>

#define T_ 128
#define B_ 64
#define E_ 1024
#define H_ 1024
#define V_ 10000
#define VP 10112              // V padded to 128 (79*128)
#define M_ (T_*B_)            // 8192
#define BH (B_*H_)
#define K3 3072               // [Ah|Ah|Al] x [Bh|Bl|Bh] 3-term split

#define GRID 128
#define NT 256

// Scratch (no allocs allowed)
__device__ float g_U0[(size_t)M_*H_];
__device__ float g_H1f[BH];                       // h1(127) fp32 for final output
__device__ unsigned int g_bar[256];
__device__ __nv_bfloat16 g_A3[(size_t)M_*K3];     // H1 split: [Ah|Ah|Al]
__device__ __nv_bfloat16 g_B3[(size_t)VP*K3];     // Wdec split: [Bh|Bl|Bh]
__device__ __nv_bfloat16 g_h0h[2][BH], g_h0l[2][BH];   // h0 double buffer, split
__device__ __nv_bfloat16 g_hid0h[BH], g_hid0l[BH];     // initial hidden layer0 split
__device__ __nv_bfloat16 g_hp1h[BH],  g_hp1l[BH];      // initial hidden layer1 split

// ===========================================================================
// fp32 GEMM (embedding projection)
// ===========================================================================
__global__ __launch_bounds__(256)
void gemm_f32(const float* __restrict__ Abase,
              const int*   __restrict__ tok,
              const float* __restrict__ W,
              const float* __restrict__ bias,
              float* __restrict__ C, int N, int K)
{
    __shared__ float As[16][64 + 4];
    __shared__ float Ws[16][64 + 4];

    const int tid = threadIdx.x;
    const int bm  = blockIdx.y * 64;
    const int bn  = blockIdx.x * 64;

    const int row = tid >> 2;
    const int kq  = (tid & 3) * 4;

    const int am = bm + row;
    const float* arow = tok ? (Abase + (size_t)tok[am] * K)
                            : (Abase + (size_t)am * K);
    const int wn = bn + row;
    const float* wrow = (wn < N) ? (W + (size_t)wn * K) : nullptr;

    const int tx = tid & 15, ty = tid >> 4;
    float acc[4][4];
    #pragma unroll
    for (int i = 0; i < 4; i++)
        #pragma unroll
        for (int j = 0; j < 4; j++) acc[i][j] = 0.f;

    for (int k0 = 0; k0 < K; k0 += 16) {
        float4 av = *(const float4*)(arow + k0 + kq);
        float4 wv = wrow ? *(const float4*)(wrow + k0 + kq)
                         : make_float4(0.f, 0.f, 0.f, 0.f);
        __syncthreads();
        As[kq+0][row] = av.x; As[kq+1][row] = av.y;
        As[kq+2][row] = av.z; As[kq+3][row] = av.w;
        Ws[kq+0][row] = wv.x; Ws[kq+1][row] = wv.y;
        Ws[kq+2][row] = wv.z; Ws[kq+3][row] = wv.w;
        __syncthreads();
        #pragma unroll
        for (int k = 0; k < 16; k++) {
            float4 a = *(const float4*)&As[k][ty * 4];
            float4 b = *(const float4*)&Ws[k][tx * 4];
            acc[0][0] = fmaf(a.x, b.x, acc[0][0]);
            acc[0][1] = fmaf(a.x, b.y, acc[0][1]);
            acc[0][2] = fmaf(a.x, b.z, acc[0][2]);
            acc[0][3] = fmaf(a.x, b.w, acc[0][3]);
            acc[1][0] = fmaf(a.y, b.x, acc[1][0]);
            acc[1][1] = fmaf(a.y, b.y, acc[1][1]);
            acc[1][2] = fmaf(a.y, b.z, acc[1][2]);
            acc[1][3] = fmaf(a.y, b.w, acc[1][3]);
            acc[2][0] = fmaf(a.z, b.x, acc[2][0]);
            acc[2][1] = fmaf(a.z, b.y, acc[2][1]);
            acc[2][2] = fmaf(a.z, b.z, acc[2][2]);
            acc[2][3] = fmaf(a.z, b.w, acc[2][3]);
            acc[3][0] = fmaf(a.w, b.x, acc[3][0]);
            acc[3][1] = fmaf(a.w, b.y, acc[3][1]);
            acc[3][2] = fmaf(a.w, b.z, acc[3][2]);
            acc[3][3] = fmaf(a.w, b.w, acc[3][3]);
        }
    }

    const int cm = bm + ty * 4;
    const int cn = bn + tx * 4;
    #pragma unroll
    for (int i = 0; i < 4; i++) {
        #pragma unroll
        for (int j = 0; j < 4; j++) {
            int n = cn + j;
            if (n < N) {
                float v = acc[i][j];
                if (bias) v += bias[n];
                C[(size_t)(cm + i) * N + n] = v;
            }
        }
    }
}

// ===========================================================================
// Grid barrier + helpers
// ===========================================================================
__global__ void reset_bar_kernel() {
    if (threadIdx.x < 256) g_bar[threadIdx.x] = 0;
}

__device__ __forceinline__ void gsync(int slot) {
    __syncthreads();
    if (threadIdx.x == 0) {
        __threadfence();
        atomicAdd(&g_bar[slot], 1u);
        while (*((volatile unsigned int*)&g_bar[slot]) < GRID) { }
        __threadfence();
    }
    __syncthreads();
}

__device__ __forceinline__ void split_bf16(float x, __nv_bfloat16& h, __nv_bfloat16& l) {
    h = __float2bfloat16(x);
    l = __float2bfloat16(x - __bfloat162float(h));
}

__device__ __forceinline__ uint32_t smem_u32(const void* p) {
    uint32_t a;
    asm("{ .reg .u64 t; cvta.to.shared.u64 t, %1; cvt.u32.u64 %0, t; }"
        : "=r"(a) : "l"(p));
    return a;
}
__device__ __forceinline__ void cp16(uint32_t dst, const void* src) {
    asm volatile("cp.async.cg.shared.global [%0], [%1], 16;"
                 :: "r"(dst), "l"(src));
}
__device__ __forceinline__ void ldm_x4(uint32_t& r0, uint32_t& r1,
                                       uint32_t& r2, uint32_t& r3, uint32_t addr) {
    asm volatile("ldmatrix.sync.aligned.m8n8.x4.shared.b16 {%0,%1,%2,%3}, [%4];"
                 : "=r"(r0), "=r"(r1), "=r"(r2), "=r"(r3) : "r"(addr));
}
__device__ __forceinline__ void mma16816(float* d,
                                         const uint32_t* a,
                                         uint32_t b0, uint32_t b1) {
    asm volatile("mma.sync.aligned.m16n8k16.row.col.f32.bf16.bf16.f32 "
                 "{%0,%1,%2,%3}, {%4,%5,%6,%7}, {%8,%9}, {%0,%1,%2,%3};"
                 : "+f"(d[0]), "+f"(d[1]), "+f"(d[2]), "+f"(d[3])
                 : "r"(a[0]), "r"(a[1]), "r"(a[2]), "r"(a[3]), "r"(b0), "r"(b1));
}

// ===========================================================================
// Persistent tensor-core recurrence.
//   Block b owns output columns [8b, 8b+8) of all three matrices.
//   Weights resident in smem as bf16 hi/lo: [mat][16 rows][2048B] (rows 0-7 hi,
//   8-15 lo), swizzled. h streamed in 64-k chunks (4 arrays: h0h,h0l,h1h,h1l).
//   8 warps: wg = k-half, mw = m16 tile. 3-term split per matrix.
// ===========================================================================
#define RSM_H   98304                       // after 3*32768 weight bytes
#define RSM_RED (RSM_H + 65536)
#define RSM_TOTAL (RSM_RED + 4608)

#define LOADCH(ch, buf) do {                                                   \
    const int seg_ = tid & 7;                                                  \
    const int r0_  = tid >> 3;                                                 \
    _Pragma("unroll")                                                          \
    for (int i_ = 0; i_ < 8; i_++) {                                           \
        const int arr_ = i_ >> 1;                                              \
        const int row_ = r0_ + (i_ & 1) * 32;                                  \
        const char* src_ =                                                     \
          (arr_ == 0) ? (const char*)h0h + ((size_t)row_*H_  + (size_t)(ch)*64 + seg_*8)*2 : \
          (arr_ == 1) ? (const char*)h0l + ((size_t)row_*H_  + (size_t)(ch)*64 + seg_*8)*2 : \
          (arr_ == 2) ? (const char*)h1h + ((size_t)row_*h1s + (size_t)(ch)*64 + seg_*8)*2 : \
                        (const char*)h1l + ((size_t)row_*h1s + (size_t)(ch)*64 + seg_*8)*2;  \
        cp16(sb + RSM_H + (buf)*32768 + arr_*8192 + row_*128                   \
                 + (uint32_t)((seg_*16) ^ ((row_ & 7) << 4)), src_);           \
    }                                                                          \
    asm volatile("cp.async.commit_group;");                                    \
} while (0)

__global__ __launch_bounds__(256, 1)
void rnn_persistent_mma(const float* __restrict__ Wh0,
                        const float* __restrict__ Win1,
                        const float* __restrict__ Wh1,
                        const float* __restrict__ b1v,
                        const float* __restrict__ hidden)
{
    extern __shared__ char rsm[];
    const uint32_t sb = smem_u32(rsm);
    const int tid = threadIdx.x, lane = tid & 31, wid = tid >> 5;
    const int wg = wid >> 2, mw = wid & 3;
    const int n0 = blockIdx.x * 8;

    // --- split weights into smem (once per launch) ---
    {
        const float* Wm[3] = {Wh0, Win1, Wh1};
        #pragma unroll 1
        for (int m = 0; m < 3; ++m) {
            const float* src = Wm[m] + (size_t)n0 * H_;
            for (int idx = tid; idx < 8 * H_; idx += 256) {
                int r = idx >> 10, k = idx & 1023;
                float v = src[(size_t)r * H_ + k];
                __nv_bfloat16 hh, ll; split_bf16(v, hh, ll);
                uint32_t off = (uint32_t)(2 * k) ^ ((r & 7) << 4);
                *(__nv_bfloat16*)(rsm + m*32768 + r*2048 + off)     = hh;
                *(__nv_bfloat16*)(rsm + m*32768 + (r+8)*2048 + off) = ll;
            }
        }
    }
    // --- convert initial hidden to split bf16 ---
    for (size_t i = (size_t)blockIdx.x * 256 + tid; i < 2 * (size_t)BH;
         i += (size_t)GRID * 256) {
        __nv_bfloat16 hh, ll; split_bf16(hidden[i], hh, ll);
        if (i < (size_t)BH) { g_hid0h[i] = hh; g_hid0l[i] = ll; }
        else                { g_hp1h[i - BH] = hh; g_hp1l[i - BH] = ll; }
    }
    gsync(0);

    const float b1c0 = b1v[n0 + (lane & 3) * 2];
    const float b1c1 = b1v[n0 + (lane & 3) * 2 + 1];

    // tt = -1: prologue (h0(0) only). tt in [0,128): h1(tt) + h0(tt+1).
    for (int tt = -1; tt < T_; ++tt) {
        const __nv_bfloat16 *h0h, *h0l, *h1h, *h1l;
        size_t h1s;
        if (tt < 0) { h0h = g_hid0h; h0l = g_hid0l; }
        else        { h0h = g_h0h[tt & 1]; h0l = g_h0l[tt & 1]; }
        if (tt <= 0) { h1h = g_hp1h; h1l = g_hp1l; h1s = H_; }
        else { h1h = g_A3 + (size_t)(tt - 1) * B_ * K3; h1l = h1h + 2048; h1s = K3; }

        float P0[4] = {0.f,0.f,0.f,0.f}, P1[4] = {0.f,0.f,0.f,0.f};

        LOADCH(0, 0);
        for (int ch = 0; ch < 16; ++ch) {
            if (ch < 15) { LOADCH(ch + 1, (ch + 1) & 1);
                           asm volatile("cp.async.wait_group 1;"); }
            else         { asm volatile("cp.async.wait_group 0;"); }
            __syncthreads();
            const uint32_t hb = sb + RSM_H + (ch & 1) * 32768;
            #pragma unroll
            for (int k16 = 0; k16 < 2; ++k16) {
                const int kb2 = wg * 64 + k16 * 32;        // byte off in 128B row
                const int kbw = ch * 128 + kb2;            // byte off in 2048B row
                const int arow = mw * 16 + (lane & 15);
                const uint32_t aoff = (uint32_t)(kb2 + ((lane >> 4) & 1) * 16)
                                      ^ ((arow & 7) << 4);
                const int brow = ((lane >> 4) & 1) * 8 + (lane & 7);
                const uint32_t boff = (uint32_t)(kbw + ((lane >> 3) & 1) * 16)
                                      ^ ((brow & 7) << 4);

                uint32_t aH0[4], aL0[4];
                ldm_x4(aH0[0], aH0[1], aH0[2], aH0[3], hb + arow*128 + aoff);
                ldm_x4(aL0[0], aL0[1], aL0[2], aL0[3], hb + 8192 + arow*128 + aoff);
                uint32_t b0f[4];
                ldm_x4(b0f[0], b0f[1], b0f[2], b0f[3], sb + brow*2048 + boff);

                mma16816(P0, aH0, b0f[0], b0f[1]);   // hi*hi
                mma16816(P0, aH0, b0f[2], b0f[3]);   // hi*lo
                mma16816(P0, aL0, b0f[0], b0f[1]);   // lo*hi

                if (tt >= 0) {
                    uint32_t aH1[4], aL1[4];
                    ldm_x4(aH1[0], aH1[1], aH1[2], aH1[3], hb + 16384 + arow*128 + aoff);
                    ldm_x4(aL1[0], aL1[1], aL1[2], aL1[3], hb + 24576 + arow*128 + aoff);
                    uint32_t bif[4], bhf[4];
                    ldm_x4(bif[0], bif[1], bif[2], bif[3], sb + 32768 + brow*2048 + boff);
                    ldm_x4(bhf[0], bhf[1], bhf[2], bhf[3], sb + 65536 + brow*2048 + boff);

                    mma16816(P1, aH0, bif[0], bif[1]);
                    mma16816(P1, aH0, bif[2], bif[3]);
                    mma16816(P1, aL0, bif[0], bif[1]);
                    mma16816(P1, aH1, bhf[0], bhf[1]);
                    mma16816(P1, aH1, bhf[2], bhf[3]);
                    mma16816(P1, aL1, bhf[0], bhf[1]);
                }
            }
            __syncthreads();
        }

        // k-half reduction + epilogue
        float* red = (float*)(rsm + RSM_RED);
        if (wg == 1) {
            float* r = red + (mw * 32 + lane) * 9;
            r[0]=P0[0]; r[1]=P0[1]; r[2]=P0[2]; r[3]=P0[3];
            r[4]=P1[0]; r[5]=P1[1]; r[6]=P1[2]; r[7]=P1[3];
        }
        __syncthreads();
        if (wg == 0) {
            const float* r = red + (mw * 32 + lane) * 9;
            #pragma unroll
            for (int j = 0; j < 4; j++) { P0[j] += r[j]; P1[j] += r[j + 4]; }

            const int r0 = mw * 16 + (lane >> 2);
            const int c0 = n0 + (lane & 3) * 2;
            const int rws[4] = {r0, r0, r0 + 8, r0 + 8};
            const int cls[4] = {c0, c0 + 1, c0, c0 + 1};
            const float bb[4] = {b1c0, b1c1, b1c0, b1c1};

            if (tt >= 0) {
                #pragma unroll
                for (int j = 0; j < 4; j++) {
                    float v = tanhf(P1[j] + bb[j]);
                    __nv_bfloat16 hh, ll; split_bf16(v, hh, ll);
                    size_t ab = ((size_t)(tt * 64 + rws[j])) * K3 + cls[j];
                    g_A3[ab] = hh; g_A3[ab + 1024] = hh; g_A3[ab + 2048] = ll;
                    if (tt == T_ - 1) g_H1f[rws[j] * H_ + cls[j]] = v;
                }
            }
            if (tt < T_ - 1) {
                __nv_bfloat16* dh = g_h0h[(tt + 1) & 1];
                __nv_bfloat16* dl = g_h0l[(tt + 1) & 1];
                #pragma unroll
                for (int j = 0; j < 4; j++) {
                    float u = g_U0[(size_t)(tt + 1) * BH + rws[j] * H_ + cls[j]];
                    float v = tanhf(P0[j] + u);
                    __nv_bfloat16 hh, ll; split_bf16(v, hh, ll);
                    dh[rws[j] * H_ + cls[j]] = hh;
                    dl[rws[j] * H_ + cls[j]] = ll;
                }
            }
        }
        gsync(tt + 2);
    }
}

// ===========================================================================
// Wdec fp32 -> bf16 [Bh|Bl|Bh] split (K3 layout, pad rows zero)
// ===========================================================================
__global__ __launch_bounds__(256)
void convert_wdec(const float* __restrict__ W, __nv_bfloat16* __restrict__ B3)
{
    size_t i = (size_t)blockIdx.x * 256 + threadIdx.x;   // over VP*1024
    int n = (int)(i >> 10);
    int k = (int)(i & 1023);
    float v = (n < V_) ? W[(size_t)n * H_ + k] : 0.f;
    __nv_bfloat16 h, l;
    split_bf16(v, h, l);
    B3[(size_t)n * K3 + k]        = h;
    B3[(size_t)n * K3 + 1024 + k] = l;
    B3[(size_t)n * K3 + 2048 + k] = h;
}

// ===========================================================================
// mma.sync bf16 decoder GEMM: C = A3 @ B3^T + bdec, K=3072 (unchanged, proven)
// ===========================================================================
#define DEC_SMEM 65536

__device__ __forceinline__ void mma16816d(float& d0, float& d1, float& d2, float& d3,
                                          uint32_t a0, uint32_t a1, uint32_t a2, uint32_t a3,
                                          uint32_t b0, uint32_t b1) {
    asm volatile("mma.sync.aligned.m16n8k16.row.col.f32.bf16.bf16.f32 "
                 "{%0,%1,%2,%3}, {%4,%5,%6,%7}, {%8,%9}, {%0,%1,%2,%3};"
                 : "+f"(d0), "+f"(d1), "+f"(d2), "+f"(d3)
                 : "r"(a0), "r"(a1), "r"(a2), "r"(a3), "r"(b0), "r"(b1));
}

__global__ __launch_bounds__(256, 1)
void decoder_mma(const __nv_bfloat16* __restrict__ A3,
                 const __nv_bfloat16* __restrict__ B3,
                 const float* __restrict__ bdec, float* __restrict__ C)
{
    extern __shared__ char dsm[];
    const uint32_t sb = smem_u32(dsm);

    const int tid  = threadIdx.x;
    const int lane = tid & 31, wid = tid >> 5;
    const int wm = wid >> 2, wn = wid & 3;
    const int m0 = blockIdx.y * 128, n0 = blockIdx.x * 128;

    float acc[4][4][4];
    #pragma unroll
    for (int i = 0; i < 4; i++)
        #pragma unroll
        for (int j = 0; j < 4; j++)
            #pragma unroll
            for (int q = 0; q < 4; q++) acc[i][j][q] = 0.f;

    int lrow[4], lcb[4];
    #pragma unroll
    for (int i = 0; i < 4; i++) {
        int idx = tid + i * 256;
        lrow[i] = idx >> 3;
        lcb[i]  = (idx & 7) * 16;
    }

    #define LOAD_TILE(ch, buf) do {                                            \
        const uint32_t Ab_ = sb + (buf) * 32768;                               \
        const uint32_t Bb_ = Ab_ + 16384;                                      \
        _Pragma("unroll")                                                      \
        for (int i_ = 0; i_ < 4; i_++) {                                       \
            int r_ = lrow[i_], cb_ = lcb[i_];                                  \
            uint32_t sw_ = (uint32_t)(cb_ ^ ((r_ & 7) << 4));                  \
            cp16(Ab_ + r_ * 128 + sw_,                                         \
                 (const char*)A3 + (((size_t)(m0 + r_) * K3 + (ch) * 64) * 2 + cb_)); \
            cp16(Bb_ + r_ * 128 + sw_,                                         \
                 (const char*)B3 + (((size_t)(n0 + r_) * K3 + (ch) * 64) * 2 + cb_)); \
        }                                                                      \
        asm volatile("cp.async.commit_group;");                                \
    } while (0)

    LOAD_TILE(0, 0);

    const int KCH = K3 / 64;   // 48
    for (int ch = 0; ch < KCH; ++ch) {
        if (ch + 1 < KCH) {
            LOAD_TILE(ch + 1, (ch + 1) & 1);
            asm volatile("cp.async.wait_group 1;");
        } else {
            asm volatile("cp.async.wait_group 0;");
        }
        __syncthreads();

        const uint32_t Ab = sb + (ch & 1) * 32768;
        const uint32_t Bb = Ab + 16384;

        #pragma unroll
        for (int ks = 0; ks < 4; ++ks) {
            const int kb2 = ks * 32;

            uint32_t b[8];
            #pragma unroll
            for (int h = 0; h < 2; ++h) {
                int nrow = wn * 32 + h * 16 + ((lane >> 4) & 1) * 8 + (lane & 7);
                int kcol = kb2 + ((lane >> 3) & 1) * 16;
                uint32_t ad = Bb + nrow * 128 + (kcol ^ ((nrow & 7) << 4));
                ldm_x4(b[4*h+0], b[4*h+1], b[4*h+2], b[4*h+3], ad);
            }

            #pragma unroll
            for (int mf = 0; mf < 4; ++mf) {
                int arow = wm * 64 + mf * 16 + (lane & 15);
                int acol = kb2 + ((lane >> 4) & 1) * 16;
                uint32_t ad = Ab + arow * 128 + (acol ^ ((arow & 7) << 4));
                uint32_t a0, a1, a2r, a3r;
                ldm_x4(a0, a1, a2r, a3r, ad);
                #pragma unroll
                for (int nf = 0; nf < 4; ++nf)
                    mma16816d(acc[mf][nf][0], acc[mf][nf][1],
                              acc[mf][nf][2], acc[mf][nf][3],
                              a0, a1, a2r, a3r, b[nf*2], b[nf*2+1]);
            }
        }
        __syncthreads();
    }

    #pragma unroll
    for (int mf = 0; mf < 4; ++mf) {
        const int r0 = m0 + wm * 64 + mf * 16 + (lane >> 2);
        #pragma unroll
        for (int nf = 0; nf < 4; ++nf) {
            const int c = n0 + wn * 32 + nf * 8 + (lane & 3) * 2;
            if (c < V_) {
                float2 bia = *(const float2*)(bdec + c);
                float2 v0 = make_float2(acc[mf][nf][0] + bia.x, acc[mf][nf][1] + bia.y);
                float2 v1 = make_float2(acc[mf][nf][2] + bia.x, acc[mf][nf][3] + bia.y);
                *(float2*)(C + (size_t)r0 * V_ + c)     = v0;
                *(float2*)(C + (size_t)(r0+8) * V_ + c) = v1;
            }
        }
    }
}

// ===========================================================================
// Final hidden state: h0(127) reconstructed from split, h1(127) fp32
// ===========================================================================
__global__ void copy_final(const __nv_bfloat16* __restrict__ h0hh,
                           const __nv_bfloat16* __restrict__ h0ll,
                           const float* __restrict__ h1f,
                           float* __restrict__ out)
{
    int i = blockIdx.x * blockDim.x + threadIdx.x;
    if (i < BH) {
        out[i]      = __bfloat162float(h0hh[i]) + __bfloat162float(h0ll[i]);
        out[BH + i] = h1f[i];
    }
}

extern "C" void kernel_launch(void* const* d_in, const int* in_sizes, int n_in,
                              void* d_out, int out_size)
{
    const float* emb    = (const float*)d_in[0];
    const float* W_in0  = (const float*)d_in[1];
    const float* Wh0    = (const float*)d_in[2];
    const float* b0     = (const float*)d_in[3];
    const float* W_in1  = (const float*)d_in[4];
    const float* Wh1    = (const float*)d_in[5];
    const float* b1     = (const float*)d_in[6];
    const float* Wdec   = (const float*)d_in[7];
    const float* bdec   = (const float*)d_in[8];
    const float* hidden = (const float*)d_in[9];
    const int*   tokens = (const int*)d_in[10];

    float* out    = (float*)d_out;
    float* logits = out;
    float* hfin   = out + (size_t)M_ * V_;

    float *U0 = nullptr, *H1f = nullptr;
    __nv_bfloat16 *A3 = nullptr, *B3 = nullptr, *h0h = nullptr, *h0l = nullptr;
    cudaGetSymbolAddress((void**)&U0,  g_U0);
    cudaGetSymbolAddress((void**)&H1f, g_H1f);
    cudaGetSymbolAddress((void**)&A3,  g_A3);
    cudaGetSymbolAddress((void**)&B3,  g_B3);
    cudaGetSymbolAddress((void**)&h0h, g_h0h);
    cudaGetSymbolAddress((void**)&h0l, g_h0l);

    cudaFuncSetAttribute(rnn_persistent_mma,
                         cudaFuncAttributeMaxDynamicSharedMemorySize, RSM_TOTAL);
    cudaFuncSetAttribute(decoder_mma,
                         cudaFuncAttributeMaxDynamicSharedMemorySize, DEC_SMEM);

    // 0) Wdec -> bf16 [Bh|Bl|Bh] (independent)
    convert_wdec<<<(int)(((size_t)VP * 1024) / 256), 256>>>(Wdec, B3);

    // 1) U0 = emb[tokens] @ W_in0^T + b0
    gemm_f32<<<dim3(H_ / 64, M_ / 64), 256>>>(emb, tokens, W_in0, b0, U0, H_, E_);

    // 2) Persistent tensor-core recurrence (writes A3 + h0 splits + H1f)
    reset_bar_kernel<<<1, 256>>>();
    rnn_persistent_mma<<<GRID, NT, RSM_TOTAL>>>(Wh0, W_in1, Wh1, b1, hidden);

    // 3) logits = A3 @ B3^T + bdec via mma.sync bf16 (K=3072, 3-term split)
    decoder_mma<<<dim3(VP / 128, M_ / 128), 256, DEC_SMEM>>>(A3, B3, bdec, logits);

    // 4) final hidden states: h0(127) in split buffer parity 1, h1(127) in H1f
    copy_final<<<(BH + 255) / 256, 256>>>(h0h + BH /*g_h0h[1]*/, h0l + BH,
                                          H1f, hfin);

    (void)b0; (void)in_sizes; (void)n_in; (void)out_size;
}

// round 7
// speedup vs baseline: 4.5445x; 1.1971x over previous
#include <cuda_runtime.h>
#include <cuda_bf16.h>
#include <math.h>
#include <stdint.h>

#define T_ 128
#define B_ 64
#define E_ 1024
#define H_ 1024
#define V_ 10000
#define VP 10112              // V padded to 128 (79*128)
#define M_ (T_*B_)            // 8192
#define BH (B_*H_)
#define K3 3072               // [Ah|Ah|Al] x [Bh|Bl|Bh] 3-term split

#define GRID 128
#define NT 256

// Scratch (no allocs allowed)
__device__ float g_U0[(size_t)M_*H_];
__device__ float g_H1f[BH];                       // h1(127) fp32 for final output
__device__ unsigned int g_bar[256];
__device__ __nv_bfloat16 g_A3[(size_t)M_*K3];     // H1 split: [Ah|Ah|Al]
__device__ __nv_bfloat16 g_B3[(size_t)VP*K3];     // Wdec split: [Bh|Bl|Bh]
__device__ __nv_bfloat16 g_h0h[2][BH], g_h0l[2][BH];   // h0 double buffer, split
__device__ __nv_bfloat16 g_hid0h[BH], g_hid0l[BH];     // initial hidden layer0 split
__device__ __nv_bfloat16 g_hp1h[BH],  g_hp1l[BH];      // initial hidden layer1 split
__device__ __nv_bfloat16 g_embH[(size_t)V_*E_];        // emb table hi
__device__ __nv_bfloat16 g_embL[(size_t)V_*E_];        // emb table lo
__device__ __nv_bfloat16 g_W03[(size_t)H_*K3];         // W_in0 split [Bh|Bl|Bh]

// ===========================================================================
// Grid barrier + helpers
// ===========================================================================
__global__ void reset_bar_kernel() {
    if (threadIdx.x < 256) g_bar[threadIdx.x] = 0;
}

__device__ __forceinline__ void gsync(int slot) {
    __syncthreads();
    if (threadIdx.x == 0) {
        __threadfence();
        atomicAdd(&g_bar[slot], 1u);
        while (*((volatile unsigned int*)&g_bar[slot]) < GRID) { }
        __threadfence();
    }
    __syncthreads();
}

__device__ __forceinline__ void split_bf16(float x, __nv_bfloat16& h, __nv_bfloat16& l) {
    h = __float2bfloat16(x);
    l = __float2bfloat16(x - __bfloat162float(h));
}

__device__ __forceinline__ uint32_t smem_u32(const void* p) {
    uint32_t a;
    asm("{ .reg .u64 t; cvta.to.shared.u64 t, %1; cvt.u32.u64 %0, t; }"
        : "=r"(a) : "l"(p));
    return a;
}
__device__ __forceinline__ void cp16(uint32_t dst, const void* src) {
    asm volatile("cp.async.cg.shared.global [%0], [%1], 16;"
                 :: "r"(dst), "l"(src));
}
__device__ __forceinline__ void ldm_x4(uint32_t& r0, uint32_t& r1,
                                       uint32_t& r2, uint32_t& r3, uint32_t addr) {
    asm volatile("ldmatrix.sync.aligned.m8n8.x4.shared.b16 {%0,%1,%2,%3}, [%4];"
                 : "=r"(r0), "=r"(r1), "=r"(r2), "=r"(r3) : "r"(addr));
}
__device__ __forceinline__ void mma16816(float* d,
                                         const uint32_t* a,
                                         uint32_t b0, uint32_t b1) {
    asm volatile("mma.sync.aligned.m16n8k16.row.col.f32.bf16.bf16.f32 "
                 "{%0,%1,%2,%3}, {%4,%5,%6,%7}, {%8,%9}, {%0,%1,%2,%3};"
                 : "+f"(d[0]), "+f"(d[1]), "+f"(d[2]), "+f"(d[3])
                 : "r"(a[0]), "r"(a[1]), "r"(a[2]), "r"(a[3]), "r"(b0), "r"(b1));
}
__device__ __forceinline__ void mma16816d(float& d0, float& d1, float& d2, float& d3,
                                          uint32_t a0, uint32_t a1, uint32_t a2, uint32_t a3,
                                          uint32_t b0, uint32_t b1) {
    asm volatile("mma.sync.aligned.m16n8k16.row.col.f32.bf16.bf16.f32 "
                 "{%0,%1,%2,%3}, {%4,%5,%6,%7}, {%8,%9}, {%0,%1,%2,%3};"
                 : "+f"(d0), "+f"(d1), "+f"(d2), "+f"(d3)
                 : "r"(a0), "r"(a1), "r"(a2), "r"(a3), "r"(b0), "r"(b1));
}

// ===========================================================================
// Conversion kernels
// ===========================================================================
__global__ __launch_bounds__(256)
void convert_emb(const float* __restrict__ Wemb,
                 __nv_bfloat16* __restrict__ eh, __nv_bfloat16* __restrict__ el)
{
    size_t i = (size_t)blockIdx.x * 256 + threadIdx.x;
    if (i < (size_t)V_ * E_) {
        __nv_bfloat16 h, l; split_bf16(Wemb[i], h, l);
        eh[i] = h; el[i] = l;
    }
}

__global__ __launch_bounds__(256)
void convert_win0(const float* __restrict__ W, __nv_bfloat16* __restrict__ W3)
{
    size_t i = (size_t)blockIdx.x * 256 + threadIdx.x;   // over H_*1024
    int n = (int)(i >> 10), k = (int)(i & 1023);
    __nv_bfloat16 h, l; split_bf16(W[(size_t)n * E_ + k], h, l);
    W3[(size_t)n * K3 + k]        = h;
    W3[(size_t)n * K3 + 1024 + k] = l;
    W3[(size_t)n * K3 + 2048 + k] = h;
}

__global__ __launch_bounds__(256)
void convert_wdec(const float* __restrict__ W, __nv_bfloat16* __restrict__ B3)
{
    size_t i = (size_t)blockIdx.x * 256 + threadIdx.x;   // over VP*1024
    int n = (int)(i >> 10);
    int k = (int)(i & 1023);
    float v = (n < V_) ? W[(size_t)n * H_ + k] : 0.f;
    __nv_bfloat16 h, l;
    split_bf16(v, h, l);
    B3[(size_t)n * K3 + k]        = h;
    B3[(size_t)n * K3 + 1024 + k] = l;
    B3[(size_t)n * K3 + 2048 + k] = h;
}

// ===========================================================================
// Embedding projection via mma.sync: U0 = emb[tokens] @ W_in0^T + b0
// A gathered from embH/embL by token (3-term chunk schedule), B = g_W03.
// CTA 128x128, 8 warps, BK=64, cp.async double-buffer. N=1024, K=3072.
// ===========================================================================
#define DEC_SMEM 65536

__global__ __launch_bounds__(256, 2)
void embed_mma(const __nv_bfloat16* __restrict__ EH,
               const __nv_bfloat16* __restrict__ EL,
               const __nv_bfloat16* __restrict__ W3,
               const int* __restrict__ tokens,
               const float* __restrict__ b0, float* __restrict__ C)
{
    extern __shared__ char dsm[];
    const uint32_t sb = smem_u32(dsm);

    const int tid  = threadIdx.x;
    const int lane = tid & 31, wid = tid >> 5;
    const int wm = wid >> 2, wn = wid & 3;
    const int m0 = blockIdx.y * 128, n0 = blockIdx.x * 128;

    float acc[4][4][4];
    #pragma unroll
    for (int i = 0; i < 4; i++)
        #pragma unroll
        for (int j = 0; j < 4; j++)
            #pragma unroll
            for (int q = 0; q < 4; q++) acc[i][j][q] = 0.f;

    int lrow[4], lcb[4], tokr[4];
    #pragma unroll
    for (int i = 0; i < 4; i++) {
        int idx = tid + i * 256;
        lrow[i] = idx >> 3;
        lcb[i]  = (idx & 7) * 16;
        tokr[i] = tokens[m0 + lrow[i]];
    }

    // chunk schedule: ch<16 -> EH k=ch*64 ; ch<32 -> EH k=(ch-16)*64 ; else EL
    #define LOAD_TILE_E(ch, buf) do {                                          \
        const uint32_t Ab_ = sb + (buf) * 32768;                               \
        const uint32_t Bb_ = Ab_ + 16384;                                      \
        const __nv_bfloat16* Aarr_ = ((ch) < 32) ? EH : EL;                    \
        const int kc_ = (((ch) < 16) ? (ch) : (((ch) < 32) ? (ch) - 16 : (ch) - 32)) * 64; \
        _Pragma("unroll")                                                      \
        for (int i_ = 0; i_ < 4; i_++) {                                       \
            int r_ = lrow[i_], cb_ = lcb[i_];                                  \
            uint32_t sw_ = (uint32_t)(cb_ ^ ((r_ & 7) << 4));                  \
            cp16(Ab_ + r_ * 128 + sw_,                                         \
                 (const char*)Aarr_ + (((size_t)tokr[i_] * E_ + kc_) * 2 + cb_)); \
            cp16(Bb_ + r_ * 128 + sw_,                                         \
                 (const char*)W3 + (((size_t)(n0 + r_) * K3 + (ch) * 64) * 2 + cb_)); \
        }                                                                      \
        asm volatile("cp.async.commit_group;");                                \
    } while (0)

    LOAD_TILE_E(0, 0);

    const int KCH = K3 / 64;   // 48
    for (int ch = 0; ch < KCH; ++ch) {
        if (ch + 1 < KCH) {
            LOAD_TILE_E(ch + 1, (ch + 1) & 1);
            asm volatile("cp.async.wait_group 1;");
        } else {
            asm volatile("cp.async.wait_group 0;");
        }
        __syncthreads();

        const uint32_t Ab = sb + (ch & 1) * 32768;
        const uint32_t Bb = Ab + 16384;

        #pragma unroll
        for (int ks = 0; ks < 4; ++ks) {
            const int kb2 = ks * 32;

            uint32_t b[8];
            #pragma unroll
            for (int h = 0; h < 2; ++h) {
                int nrow = wn * 32 + h * 16 + ((lane >> 4) & 1) * 8 + (lane & 7);
                int kcol = kb2 + ((lane >> 3) & 1) * 16;
                uint32_t ad = Bb + nrow * 128 + (kcol ^ ((nrow & 7) << 4));
                ldm_x4(b[4*h+0], b[4*h+1], b[4*h+2], b[4*h+3], ad);
            }

            #pragma unroll
            for (int mf = 0; mf < 4; ++mf) {
                int arow = wm * 64 + mf * 16 + (lane & 15);
                int acol = kb2 + ((lane >> 4) & 1) * 16;
                uint32_t ad = Ab + arow * 128 + (acol ^ ((arow & 7) << 4));
                uint32_t a0, a1, a2r, a3r;
                ldm_x4(a0, a1, a2r, a3r, ad);
                #pragma unroll
                for (int nf = 0; nf < 4; ++nf)
                    mma16816d(acc[mf][nf][0], acc[mf][nf][1],
                              acc[mf][nf][2], acc[mf][nf][3],
                              a0, a1, a2r, a3r, b[nf*2], b[nf*2+1]);
            }
        }
        __syncthreads();
    }

    #pragma unroll
    for (int mf = 0; mf < 4; ++mf) {
        const int r0 = m0 + wm * 64 + mf * 16 + (lane >> 2);
        #pragma unroll
        for (int nf = 0; nf < 4; ++nf) {
            const int c = n0 + wn * 32 + nf * 8 + (lane & 3) * 2;
            float2 bia = *(const float2*)(b0 + c);
            float2 v0 = make_float2(acc[mf][nf][0] + bia.x, acc[mf][nf][1] + bia.y);
            float2 v1 = make_float2(acc[mf][nf][2] + bia.x, acc[mf][nf][3] + bia.y);
            *(float2*)(C + (size_t)r0 * H_ + c)     = v0;
            *(float2*)(C + (size_t)(r0+8) * H_ + c) = v1;
        }
    }
}

// ===========================================================================
// Persistent tensor-core recurrence (round 6, unchanged — proven)
// ===========================================================================
#define RSM_H   98304
#define RSM_RED (RSM_H + 65536)
#define RSM_TOTAL (RSM_RED + 4608)

#define LOADCH(ch, buf) do {                                                   \
    const int seg_ = tid & 7;                                                  \
    const int r0_  = tid >> 3;                                                 \
    _Pragma("unroll")                                                          \
    for (int i_ = 0; i_ < 8; i_++) {                                           \
        const int arr_ = i_ >> 1;                                              \
        const int row_ = r0_ + (i_ & 1) * 32;                                  \
        const char* src_ =                                                     \
          (arr_ == 0) ? (const char*)h0h + ((size_t)row_*H_  + (size_t)(ch)*64 + seg_*8)*2 : \
          (arr_ == 1) ? (const char*)h0l + ((size_t)row_*H_  + (size_t)(ch)*64 + seg_*8)*2 : \
          (arr_ == 2) ? (const char*)h1h + ((size_t)row_*h1s + (size_t)(ch)*64 + seg_*8)*2 : \
                        (const char*)h1l + ((size_t)row_*h1s + (size_t)(ch)*64 + seg_*8)*2;  \
        cp16(sb + RSM_H + (buf)*32768 + arr_*8192 + row_*128                   \
                 + (uint32_t)((seg_*16) ^ ((row_ & 7) << 4)), src_);           \
    }                                                                          \
    asm volatile("cp.async.commit_group;");                                    \
} while (0)

__global__ __launch_bounds__(256, 1)
void rnn_persistent_mma(const float* __restrict__ Wh0,
                        const float* __restrict__ Win1,
                        const float* __restrict__ Wh1,
                        const float* __restrict__ b1v,
                        const float* __restrict__ hidden)
{
    extern __shared__ char rsm[];
    const uint32_t sb = smem_u32(rsm);
    const int tid = threadIdx.x, lane = tid & 31, wid = tid >> 5;
    const int wg = wid >> 2, mw = wid & 3;
    const int n0 = blockIdx.x * 8;

    {
        const float* Wm[3] = {Wh0, Win1, Wh1};
        #pragma unroll 1
        for (int m = 0; m < 3; ++m) {
            const float* src = Wm[m] + (size_t)n0 * H_;
            for (int idx = tid; idx < 8 * H_; idx += 256) {
                int r = idx >> 10, k = idx & 1023;
                float v = src[(size_t)r * H_ + k];
                __nv_bfloat16 hh, ll; split_bf16(v, hh, ll);
                uint32_t off = (uint32_t)(2 * k) ^ ((r & 7) << 4);
                *(__nv_bfloat16*)(rsm + m*32768 + r*2048 + off)     = hh;
                *(__nv_bfloat16*)(rsm + m*32768 + (r+8)*2048 + off) = ll;
            }
        }
    }
    for (size_t i = (size_t)blockIdx.x * 256 + tid; i < 2 * (size_t)BH;
         i += (size_t)GRID * 256) {
        __nv_bfloat16 hh, ll; split_bf16(hidden[i], hh, ll);
        if (i < (size_t)BH) { g_hid0h[i] = hh; g_hid0l[i] = ll; }
        else                { g_hp1h[i - BH] = hh; g_hp1l[i - BH] = ll; }
    }
    gsync(0);

    const float b1c0 = b1v[n0 + (lane & 3) * 2];
    const float b1c1 = b1v[n0 + (lane & 3) * 2 + 1];

    for (int tt = -1; tt < T_; ++tt) {
        const __nv_bfloat16 *h0h, *h0l, *h1h, *h1l;
        size_t h1s;
        if (tt < 0) { h0h = g_hid0h; h0l = g_hid0l; }
        else        { h0h = g_h0h[tt & 1]; h0l = g_h0l[tt & 1]; }
        if (tt <= 0) { h1h = g_hp1h; h1l = g_hp1l; h1s = H_; }
        else { h1h = g_A3 + (size_t)(tt - 1) * B_ * K3; h1l = h1h + 2048; h1s = K3; }

        float P0[4] = {0.f,0.f,0.f,0.f}, P1[4] = {0.f,0.f,0.f,0.f};

        LOADCH(0, 0);
        for (int ch = 0; ch < 16; ++ch) {
            if (ch < 15) { LOADCH(ch + 1, (ch + 1) & 1);
                           asm volatile("cp.async.wait_group 1;"); }
            else         { asm volatile("cp.async.wait_group 0;"); }
            __syncthreads();
            const uint32_t hb = sb + RSM_H + (ch & 1) * 32768;
            #pragma unroll
            for (int k16 = 0; k16 < 2; ++k16) {
                const int kb2 = wg * 64 + k16 * 32;
                const int kbw = ch * 128 + kb2;
                const int arow = mw * 16 + (lane & 15);
                const uint32_t aoff = (uint32_t)(kb2 + ((lane >> 4) & 1) * 16)
                                      ^ ((arow & 7) << 4);
                const int brow = ((lane >> 4) & 1) * 8 + (lane & 7);
                const uint32_t boff = (uint32_t)(kbw + ((lane >> 3) & 1) * 16)
                                      ^ ((brow & 7) << 4);

                uint32_t aH0[4], aL0[4];
                ldm_x4(aH0[0], aH0[1], aH0[2], aH0[3], hb + arow*128 + aoff);
                ldm_x4(aL0[0], aL0[1], aL0[2], aL0[3], hb + 8192 + arow*128 + aoff);
                uint32_t b0f[4];
                ldm_x4(b0f[0], b0f[1], b0f[2], b0f[3], sb + brow*2048 + boff);

                mma16816(P0, aH0, b0f[0], b0f[1]);
                mma16816(P0, aH0, b0f[2], b0f[3]);
                mma16816(P0, aL0, b0f[0], b0f[1]);

                if (tt >= 0) {
                    uint32_t aH1[4], aL1[4];
                    ldm_x4(aH1[0], aH1[1], aH1[2], aH1[3], hb + 16384 + arow*128 + aoff);
                    ldm_x4(aL1[0], aL1[1], aL1[2], aL1[3], hb + 24576 + arow*128 + aoff);
                    uint32_t bif[4], bhf[4];
                    ldm_x4(bif[0], bif[1], bif[2], bif[3], sb + 32768 + brow*2048 + boff);
                    ldm_x4(bhf[0], bhf[1], bhf[2], bhf[3], sb + 65536 + brow*2048 + boff);

                    mma16816(P1, aH0, bif[0], bif[1]);
                    mma16816(P1, aH0, bif[2], bif[3]);
                    mma16816(P1, aL0, bif[0], bif[1]);
                    mma16816(P1, aH1, bhf[0], bhf[1]);
                    mma16816(P1, aH1, bhf[2], bhf[3]);
                    mma16816(P1, aL1, bhf[0], bhf[1]);
                }
            }
            __syncthreads();
        }

        float* red = (float*)(rsm + RSM_RED);
        if (wg == 1) {
            float* r = red + (mw * 32 + lane) * 9;
            r[0]=P0[0]; r[1]=P0[1]; r[2]=P0[2]; r[3]=P0[3];
            r[4]=P1[0]; r[5]=P1[1]; r[6]=P1[2]; r[7]=P1[3];
        }
        __syncthreads();
        if (wg == 0) {
            const float* r = red + (mw * 32 + lane) * 9;
            #pragma unroll
            for (int j = 0; j < 4; j++) { P0[j] += r[j]; P1[j] += r[j + 4]; }

            const int r0 = mw * 16 + (lane >> 2);
            const int c0 = n0 + (lane & 3) * 2;
            const int rws[4] = {r0, r0, r0 + 8, r0 + 8};
            const int cls[4] = {c0, c0 + 1, c0, c0 + 1};
            const float bb[4] = {b1c0, b1c1, b1c0, b1c1};

            if (tt >= 0) {
                #pragma unroll
                for (int j = 0; j < 4; j++) {
                    float v = tanhf(P1[j] + bb[j]);
                    __nv_bfloat16 hh, ll; split_bf16(v, hh, ll);
                    size_t ab = ((size_t)(tt * 64 + rws[j])) * K3 + cls[j];
                    g_A3[ab] = hh; g_A3[ab + 1024] = hh; g_A3[ab + 2048] = ll;
                    if (tt == T_ - 1) g_H1f[rws[j] * H_ + cls[j]] = v;
                }
            }
            if (tt < T_ - 1) {
                __nv_bfloat16* dh = g_h0h[(tt + 1) & 1];
                __nv_bfloat16* dl = g_h0l[(tt + 1) & 1];
                #pragma unroll
                for (int j = 0; j < 4; j++) {
                    float u = g_U0[(size_t)(tt + 1) * BH + rws[j] * H_ + cls[j]];
                    float v = tanhf(P0[j] + u);
                    __nv_bfloat16 hh, ll; split_bf16(v, hh, ll);
                    dh[rws[j] * H_ + cls[j]] = hh;
                    dl[rws[j] * H_ + cls[j]] = ll;
                }
            }
        }
        gsync(tt + 2);
    }
}

// ===========================================================================
// mma.sync bf16 decoder GEMM: C = A3 @ B3^T + bdec, K=3072 (now occ=2)
// ===========================================================================
__global__ __launch_bounds__(256, 2)
void decoder_mma(const __nv_bfloat16* __restrict__ A3,
                 const __nv_bfloat16* __restrict__ B3,
                 const float* __restrict__ bdec, float* __restrict__ C)
{
    extern __shared__ char dsm[];
    const uint32_t sb = smem_u32(dsm);

    const int tid  = threadIdx.x;
    const int lane = tid & 31, wid = tid >> 5;
    const int wm = wid >> 2, wn = wid & 3;
    const int m0 = blockIdx.y * 128, n0 = blockIdx.x * 128;

    float acc[4][4][4];
    #pragma unroll
    for (int i = 0; i < 4; i++)
        #pragma unroll
        for (int j = 0; j < 4; j++)
            #pragma unroll
            for (int q = 0; q < 4; q++) acc[i][j][q] = 0.f;

    int lrow[4], lcb[4];
    #pragma unroll
    for (int i = 0; i < 4; i++) {
        int idx = tid + i * 256;
        lrow[i] = idx >> 3;
        lcb[i]  = (idx & 7) * 16;
    }

    #define LOAD_TILE(ch, buf) do {                                            \
        const uint32_t Ab_ = sb + (buf) * 32768;                               \
        const uint32_t Bb_ = Ab_ + 16384;                                      \
        _Pragma("unroll")                                                      \
        for (int i_ = 0; i_ < 4; i_++) {                                       \
            int r_ = lrow[i_], cb_ = lcb[i_];                                  \
            uint32_t sw_ = (uint32_t)(cb_ ^ ((r_ & 7) << 4));                  \
            cp16(Ab_ + r_ * 128 + sw_,                                         \
                 (const char*)A3 + (((size_t)(m0 + r_) * K3 + (ch) * 64) * 2 + cb_)); \
            cp16(Bb_ + r_ * 128 + sw_,                                         \
                 (const char*)B3 + (((size_t)(n0 + r_) * K3 + (ch) * 64) * 2 + cb_)); \
        }                                                                      \
        asm volatile("cp.async.commit_group;");                                \
    } while (0)

    LOAD_TILE(0, 0);

    const int KCH = K3 / 64;   // 48
    for (int ch = 0; ch < KCH; ++ch) {
        if (ch + 1 < KCH) {
            LOAD_TILE(ch + 1, (ch + 1) & 1);
            asm volatile("cp.async.wait_group 1;");
        } else {
            asm volatile("cp.async.wait_group 0;");
        }
        __syncthreads();

        const uint32_t Ab = sb + (ch & 1) * 32768;
        const uint32_t Bb = Ab + 16384;

        #pragma unroll
        for (int ks = 0; ks < 4; ++ks) {
            const int kb2 = ks * 32;

            uint32_t b[8];
            #pragma unroll
            for (int h = 0; h < 2; ++h) {
                int nrow = wn * 32 + h * 16 + ((lane >> 4) & 1) * 8 + (lane & 7);
                int kcol = kb2 + ((lane >> 3) & 1) * 16;
                uint32_t ad = Bb + nrow * 128 + (kcol ^ ((nrow & 7) << 4));
                ldm_x4(b[4*h+0], b[4*h+1], b[4*h+2], b[4*h+3], ad);
            }

            #pragma unroll
            for (int mf = 0; mf < 4; ++mf) {
                int arow = wm * 64 + mf * 16 + (lane & 15);
                int acol = kb2 + ((lane >> 4) & 1) * 16;
                uint32_t ad = Ab + arow * 128 + (acol ^ ((arow & 7) << 4));
                uint32_t a0, a1, a2r, a3r;
                ldm_x4(a0, a1, a2r, a3r, ad);
                #pragma unroll
                for (int nf = 0; nf < 4; ++nf)
                    mma16816d(acc[mf][nf][0], acc[mf][nf][1],
                              acc[mf][nf][2], acc[mf][nf][3],
                              a0, a1, a2r, a3r, b[nf*2], b[nf*2+1]);
            }
        }
        __syncthreads();
    }

    #pragma unroll
    for (int mf = 0; mf < 4; ++mf) {
        const int r0 = m0 + wm * 64 + mf * 16 + (lane >> 2);
        #pragma unroll
        for (int nf = 0; nf < 4; ++nf) {
            const int c = n0 + wn * 32 + nf * 8 + (lane & 3) * 2;
            if (c < V_) {
                float2 bia = *(const float2*)(bdec + c);
                float2 v0 = make_float2(acc[mf][nf][0] + bia.x, acc[mf][nf][1] + bia.y);
                float2 v1 = make_float2(acc[mf][nf][2] + bia.x, acc[mf][nf][3] + bia.y);
                *(float2*)(C + (size_t)r0 * V_ + c)     = v0;
                *(float2*)(C + (size_t)(r0+8) * V_ + c) = v1;
            }
        }
    }
}

// ===========================================================================
// Final hidden state: h0(127) reconstructed from split, h1(127) fp32
// ===========================================================================
__global__ void copy_final(const __nv_bfloat16* __restrict__ h0hh,
                           const __nv_bfloat16* __restrict__ h0ll,
                           const float* __restrict__ h1f,
                           float* __restrict__ out)
{
    int i = blockIdx.x * blockDim.x + threadIdx.x;
    if (i < BH) {
        out[i]      = __bfloat162float(h0hh[i]) + __bfloat162float(h0ll[i]);
        out[BH + i] = h1f[i];
    }
}

extern "C" void kernel_launch(void* const* d_in, const int* in_sizes, int n_in,
                              void* d_out, int out_size)
{
    const float* emb    = (const float*)d_in[0];
    const float* W_in0  = (const float*)d_in[1];
    const float* Wh0    = (const float*)d_in[2];
    const float* b0     = (const float*)d_in[3];
    const float* W_in1  = (const float*)d_in[4];
    const float* Wh1    = (const float*)d_in[5];
    const float* b1     = (const float*)d_in[6];
    const float* Wdec   = (const float*)d_in[7];
    const float* bdec   = (const float*)d_in[8];
    const float* hidden = (const float*)d_in[9];
    const int*   tokens = (const int*)d_in[10];

    float* out    = (float*)d_out;
    float* logits = out;
    float* hfin   = out + (size_t)M_ * V_;

    float *U0 = nullptr, *H1f = nullptr;
    __nv_bfloat16 *A3 = nullptr, *B3 = nullptr, *h0h = nullptr, *h0l = nullptr;
    __nv_bfloat16 *EH = nullptr, *EL = nullptr, *W03 = nullptr;
    cudaGetSymbolAddress((void**)&U0,  g_U0);
    cudaGetSymbolAddress((void**)&H1f, g_H1f);
    cudaGetSymbolAddress((void**)&A3,  g_A3);
    cudaGetSymbolAddress((void**)&B3,  g_B3);
    cudaGetSymbolAddress((void**)&h0h, g_h0h);
    cudaGetSymbolAddress((void**)&h0l, g_h0l);
    cudaGetSymbolAddress((void**)&EH,  g_embH);
    cudaGetSymbolAddress((void**)&EL,  g_embL);
    cudaGetSymbolAddress((void**)&W03, g_W03);

    cudaFuncSetAttribute(rnn_persistent_mma,
                         cudaFuncAttributeMaxDynamicSharedMemorySize, RSM_TOTAL);
    cudaFuncSetAttribute(decoder_mma,
                         cudaFuncAttributeMaxDynamicSharedMemorySize, DEC_SMEM);
    cudaFuncSetAttribute(embed_mma,
                         cudaFuncAttributeMaxDynamicSharedMemorySize, DEC_SMEM);

    // 0) splits
    reset_bar_kernel<<<1, 256>>>();
    convert_emb<<<(int)(((size_t)V_ * E_ + 255) / 256), 256>>>(emb, EH, EL);
    convert_win0<<<(int)(((size_t)H_ * 1024) / 256), 256>>>(W_in0, W03);
    convert_wdec<<<(int)(((size_t)VP * 1024) / 256), 256>>>(Wdec, B3);

    // 1) U0 = emb[tokens] @ W_in0^T + b0 via mma.sync (3-term split, gathered A)
    embed_mma<<<dim3(H_ / 128, M_ / 128), 256, DEC_SMEM>>>(EH, EL, W03, tokens,
                                                           b0, U0);

    // 2) Persistent tensor-core recurrence (writes A3 + h0 splits + H1f)
    rnn_persistent_mma<<<GRID, NT, RSM_TOTAL>>>(Wh0, W_in1, Wh1, b1, hidden);

    // 3) logits = A3 @ B3^T + bdec via mma.sync bf16 (K=3072, 3-term split)
    decoder_mma<<<dim3(VP / 128, M_ / 128), 256, DEC_SMEM>>>(A3, B3, bdec, logits);

    // 4) final hidden states: h0(127) in split buffer parity 1, h1(127) in H1f
    copy_final<<<(BH + 255) / 256, 256>>>(h0h + BH /*g_h0h[1]*/, h0l + BH,
                                          H1f, hfin);

    (void)in_sizes; (void)n_in; (void)out_size;
}